// round 7
// baseline (speedup 1.0000x reference)
#include <cuda_runtime.h>
#include <cuda_bf16.h>
#include <math.h>
#include <stdint.h>

#define CTX      1024
#define BROWS    16
#define TOTAL_S  320
#define NF       256
#define D_MODEL  256
#define NHEADS   16
#define DK       16
#define DFF      1024
#define NLAYERS  4
#define TGT      96
#define SEQ      (BROWS * TOTAL_S)   // 5120
#define ATTN_SCALE 0.25f
#define LN_EPS   1e-5f

// ---------------------------------------------------------------------------
// warp MMA + cp.async helpers (sm_80+ path; tcgen05 unavailable at sm_103)
// ---------------------------------------------------------------------------
__device__ __forceinline__ uint32_t smem_u32(const void* p) {
    uint32_t a;
    asm("{ .reg .u64 t; cvta.to.shared.u64 t, %1; cvt.u32.u64 %0, t; }"
        : "=r"(a) : "l"(p));
    return a;
}
__device__ __forceinline__ void ldsm_x4(uint32_t& r0, uint32_t& r1,
                                        uint32_t& r2, uint32_t& r3, uint32_t addr) {
    asm volatile("ldmatrix.sync.aligned.m8n8.x4.shared.b16 {%0,%1,%2,%3}, [%4];"
                 : "=r"(r0), "=r"(r1), "=r"(r2), "=r"(r3) : "r"(addr));
}
__device__ __forceinline__ void mma_bf16(float* c, const uint32_t* a, const uint32_t* b) {
    asm volatile(
        "mma.sync.aligned.m16n8k16.row.col.f32.bf16.bf16.f32 "
        "{%0,%1,%2,%3}, {%4,%5,%6,%7}, {%8,%9}, {%0,%1,%2,%3};"
        : "+f"(c[0]), "+f"(c[1]), "+f"(c[2]), "+f"(c[3])
        : "r"(a[0]), "r"(a[1]), "r"(a[2]), "r"(a[3]), "r"(b[0]), "r"(b[1]));
}
#define CP_ASYNC16(dst, src) \
    asm volatile("cp.async.cg.shared.global [%0], [%1], 16;" :: "r"(dst), "l"(src))
#define CP_COMMIT() asm volatile("cp.async.commit_group;" ::: "memory")
#define CP_WAIT0()  asm volatile("cp.async.wait_group 0;" ::: "memory")

// ---------------------------------------------------------------------------
// scratch
// ---------------------------------------------------------------------------
__device__ __align__(256) float g_u[SEQ * D_MODEL];
__device__ __align__(256) float g_qkv[SEQ * 768];
__device__ __align__(256) float g_tmp[SEQ * D_MODEL];
__device__ __align__(256) float g_scores[BROWS * NHEADS * TOTAL_S * TOTAL_S];
__device__ float g_mean[BROWS];
__device__ float g_std[BROWS];
__device__ __align__(256) float g_part[D_MODEL * BROWS * TGT];
__device__ __align__(256) float g_bqkv[NLAYERS * 768];

__device__ __align__(256) __nv_bfloat16 g_u_hi[SEQ * D_MODEL];
__device__ __align__(256) __nv_bfloat16 g_u_lo[SEQ * D_MODEL];
__device__ __align__(256) __nv_bfloat16 g_o_hi[SEQ * D_MODEL];
__device__ __align__(256) __nv_bfloat16 g_o_lo[SEQ * D_MODEL];
__device__ __align__(256) __nv_bfloat16 g_h1_hi[SEQ * DFF];
__device__ __align__(256) __nv_bfloat16 g_h1_lo[SEQ * DFF];
#define WOFF_Q   0
#define WOFF_K   65536
#define WOFF_V   131072
#define WOFF_O   196608
#define WOFF_F1  262144
#define WOFF_F2  524288
#define WSTRIDE  786432
__device__ __align__(256) __nv_bfloat16 g_wt_hi[NLAYERS * WSTRIDE];
__device__ __align__(256) __nv_bfloat16 g_wt_lo[NLAYERS * WSTRIDE];

// ---------------------------------------------------------------------------
// merged weight transpose/split + bias pack (one launch)
// grid: (256 tiles, 7 kinds, 4 layers); kind 6 = bias pack
// ---------------------------------------------------------------------------
__global__ __launch_bounds__(256) void wsplit_all_kernel(
    const float* __restrict__ WQ, const float* __restrict__ WK,
    const float* __restrict__ WV, const float* __restrict__ WO,
    const float* __restrict__ F1, const float* __restrict__ F2,
    const float* __restrict__ bQ, const float* __restrict__ bK,
    const float* __restrict__ bV)
{
    int kind = blockIdx.y, l = blockIdx.z, tile = blockIdx.x;
    if (kind == 6) {
        if (tile >= 3) return;
        int i = tile * 256 + threadIdx.x;
        if (i >= 768) return;
        float v = (i < 256) ? bQ[l * 256 + i]
                : (i < 512) ? bK[l * 256 + i - 256]
                            : bV[l * 256 + i - 512];
        g_bqkv[l * 768 + i] = v;
        return;
    }
    const float* W; int R, C; size_t inl, ooff;
    switch (kind) {
        case 0: W = WQ; R = 256;  C = 256;  inl = 65536;  ooff = WOFF_Q;  break;
        case 1: W = WK; R = 256;  C = 256;  inl = 65536;  ooff = WOFF_K;  break;
        case 2: W = WV; R = 256;  C = 256;  inl = 65536;  ooff = WOFF_V;  break;
        case 3: W = WO; R = 256;  C = 256;  inl = 65536;  ooff = WOFF_O;  break;
        case 4: W = F1; R = 256;  C = 1024; inl = 262144; ooff = WOFF_F1; break;
        default: W = F2; R = 1024; C = 256; inl = 262144; ooff = WOFF_F2; break;
    }
    int ct = C >> 5, rt = R >> 5;
    if (tile >= ct * rt) return;
    int c0 = (tile % ct) << 5, r0 = (tile / ct) << 5;
    const float* Wl = W + (size_t)l * inl;

    __shared__ float t[32][33];
    int tx = threadIdx.x & 31, ty = threadIdx.x >> 5;
#pragma unroll
    for (int i = 0; i < 32; i += 8)
        t[ty + i][tx] = Wl[(size_t)(r0 + ty + i) * C + c0 + tx];
    __syncthreads();
#pragma unroll
    for (int i = 0; i < 32; i += 8) {
        float x = t[tx][ty + i];
        size_t oi = (size_t)l * WSTRIDE + ooff + (size_t)(c0 + ty + i) * R + (r0 + tx);
        __nv_bfloat16 h = __float2bfloat16(x);
        g_wt_hi[oi] = h;
        g_wt_lo[oi] = __float2bfloat16(x - __bfloat162float(h));
    }
}

// ---------------------------------------------------------------------------
__global__ __launch_bounds__(256) void stats_kernel(const float* __restrict__ z) {
    int r = blockIdx.x;
    int tid = threadIdx.x;
    float s = 0.f, s2 = 0.f;
    for (int i = tid; i < CTX; i += 256) {
        float v = z[r * CTX + i];
        s += v; s2 += v * v;
    }
    __shared__ float rs[256], rq[256];
    rs[tid] = s; rq[tid] = s2;
    __syncthreads();
    for (int o = 128; o; o >>= 1) {
        if (tid < o) { rs[tid] += rs[tid + o]; rq[tid] += rq[tid + o]; }
        __syncthreads();
    }
    if (tid == 0) {
        float m = rs[0] / CTX;
        float var = rq[0] / CTX - m * m;
        g_mean[r] = m;
        g_std[r]  = sqrtf(var + LN_EPS);
    }
}

// ---------------------------------------------------------------------------
__global__ __launch_bounds__(256) void embed_kernel(
    const float* __restrict__ z,
    const float* __restrict__ revin_w, const float* __restrict__ revin_b,
    const float* __restrict__ Wf, const float* __restrict__ bf,
    const float* __restrict__ Wc, const float* __restrict__ bcoarse,
    const float* __restrict__ Wpos)
{
    int bch = blockIdx.y;
    int s   = blockIdx.x;
    int d   = threadIdx.x;
    int c   = bch & 7;

    __shared__ float patch[32];
    int plen, stride, p;
    const float* W; const float* bias;
    if (s < NF) { plen = 8;  stride = 4;  p = s;      W = Wf; bias = bf; }
    else        { plen = 32; stride = 16; p = s - NF; W = Wc; bias = bcoarse; }

    if (d < plen) {
        int t = p * stride + d;
        if (t > CTX - 1) t = CTX - 1;
        float zv = z[bch * CTX + t];
        patch[d] = (zv - g_mean[bch]) / g_std[bch] * revin_w[c] + revin_b[c];
    }
    __syncthreads();

    float acc = bias[d] + Wpos[s * D_MODEL + d];
    for (int i = 0; i < plen; i++) acc += patch[i] * W[i * D_MODEL + d];
    size_t idx = (size_t)(bch * TOTAL_S + s) * D_MODEL + d;
    g_u[idx] = acc;
    __nv_bfloat16 h = __float2bfloat16(acc);
    g_u_hi[idx] = h;
    g_u_lo[idx] = __float2bfloat16(acc - __bfloat162float(h));
}

// ---------------------------------------------------------------------------
// HMMA bf16x3 GEMM, cp.async 2-stage pipeline. K-chunk 32 (smem halved for
// 2 CTAs/SM occupancy). MT = CTA M-tile (64|128). Row stride 80B keeps
// ldmatrix 16B-aligned; banks of r*80%128 distinct for r=0..7.
// ---------------------------------------------------------------------------
#define RSTRIDE 80   // bytes per 32-elem bf16 row (64B data + 16B pad)

template<int EPI, int MT>
__global__ __launch_bounds__(256, 2) void gemm_tc(
    const __nv_bfloat16* __restrict__ Ah, const __nv_bfloat16* __restrict__ Al,
    const __nv_bfloat16* __restrict__ Bh, const __nv_bfloat16* __restrict__ Bl,
    const float* __restrict__ bias,
    float* __restrict__ Cf,
    __nv_bfloat16* __restrict__ Chi, __nv_bfloat16* __restrict__ Clo,
    int N, int K)
{
    constexpr int WNs = (MT == 128) ? 2 : 4;
    constexpr int NT  = 16 / WNs;
    constexpr int BUF_A = MT * RSTRIDE;
    constexpr int BUF_B = 128 * RSTRIDE;
    constexpr int STAGE = 2 * BUF_A + 2 * BUF_B;

    extern __shared__ char smem[];
    const uint32_t sbase = smem_u32(smem);

    const int tid = threadIdx.x;
    const int bm = blockIdx.y * MT, bn = blockIdx.x * 128;
    const int warp = tid >> 5, lane = tid & 31;
    const int wm = warp / WNs, wn = warp % WNs;

    const int sr2 = tid >> 2;            // 0..63 staging row
    const int scb = (tid & 3) * 16;      // byte col in smem row
    const int sce = (tid & 3) * 8;       // elem col in gmem row

    float acc[2][NT][4];
#pragma unroll
    for (int mt = 0; mt < 2; mt++)
#pragma unroll
        for (int nt = 0; nt < NT; nt++)
#pragma unroll
            for (int i = 0; i < 4; i++) acc[mt][nt][i] = 0.f;

    const int gg = lane >> 3, l7 = lane & 7;
    const int a_row = (gg & 1) * 8 + l7;
    const int a_kb  = (gg >> 1) * 16;
    const int b_row = (gg >> 1) * 8 + l7;
    const int b_kb  = (gg & 1) * 16;

    const int nchunk = K >> 5;

#define STAGE_LOAD(kc, s) do { \
        const int _k0 = (kc) << 5; \
        uint32_t _base = sbase + (s) * STAGE; \
        _Pragma("unroll") \
        for (int i = 0; i < MT / 64; i++) { \
            int r = sr2 + i * 64; \
            uint32_t so = _base + r * RSTRIDE + scb; \
            CP_ASYNC16(so, Ah + (size_t)(bm + r) * K + _k0 + sce); \
            CP_ASYNC16(so + BUF_A, Al + (size_t)(bm + r) * K + _k0 + sce); \
        } \
        _Pragma("unroll") \
        for (int i = 0; i < 2; i++) { \
            int r = sr2 + i * 64; \
            uint32_t so = _base + 2 * BUF_A + r * RSTRIDE + scb; \
            CP_ASYNC16(so, Bh + (size_t)(bn + r) * K + _k0 + sce); \
            CP_ASYNC16(so + BUF_B, Bl + (size_t)(bn + r) * K + _k0 + sce); \
        } \
        CP_COMMIT(); \
    } while (0)

    STAGE_LOAD(0, 0);

    for (int kc = 0; kc < nchunk; kc++) {
        CP_WAIT0();
        __syncthreads();
        if (kc + 1 < nchunk) STAGE_LOAD(kc + 1, (kc + 1) & 1);

        const uint32_t base = sbase + (kc & 1) * STAGE;
        const uint32_t uAh = base, uAl = base + BUF_A;
        const uint32_t uBh = base + 2 * BUF_A, uBl = uBh + BUF_B;

#pragma unroll
        for (int ks = 0; ks < 2; ks++) {
            uint32_t ah[2][4], al[2][4], bh[NT][2], bl[NT][2];
#pragma unroll
            for (int mt = 0; mt < 2; mt++) {
                int row = wm * 32 + mt * 16 + a_row;
                uint32_t off = (uint32_t)(row * RSTRIDE + ks * 32 + a_kb);
                ldsm_x4(ah[mt][0], ah[mt][1], ah[mt][2], ah[mt][3], uAh + off);
                ldsm_x4(al[mt][0], al[mt][1], al[mt][2], al[mt][3], uAl + off);
            }
#pragma unroll
            for (int j = 0; j < NT / 2; j++) {
                int row = wn * (128 / WNs) + j * 16 + b_row;
                uint32_t off = (uint32_t)(row * RSTRIDE + ks * 32 + b_kb);
                uint32_t r0, r1, r2, r3;
                ldsm_x4(r0, r1, r2, r3, uBh + off);
                bh[2 * j][0] = r0; bh[2 * j][1] = r1;
                bh[2 * j + 1][0] = r2; bh[2 * j + 1][1] = r3;
                ldsm_x4(r0, r1, r2, r3, uBl + off);
                bl[2 * j][0] = r0; bl[2 * j][1] = r1;
                bl[2 * j + 1][0] = r2; bl[2 * j + 1][1] = r3;
            }
#pragma unroll
            for (int mt = 0; mt < 2; mt++)
#pragma unroll
                for (int nt = 0; nt < NT; nt++) {
                    mma_bf16(acc[mt][nt], ah[mt], bh[nt]);
                    mma_bf16(acc[mt][nt], ah[mt], bl[nt]);
                    mma_bf16(acc[mt][nt], al[mt], bh[nt]);
                }
        }
        __syncthreads();
    }
#undef STAGE_LOAD

#pragma unroll
    for (int mt = 0; mt < 2; mt++) {
        int row0 = bm + wm * 32 + mt * 16 + (lane >> 2);
#pragma unroll
        for (int nt = 0; nt < NT; nt++) {
            int col = bn + wn * (128 / WNs) + nt * 8 + (lane & 3) * 2;
            float b0 = bias[col], b1 = bias[col + 1];
            float v0 = acc[mt][nt][0] + b0, v1 = acc[mt][nt][1] + b1;
            float v2 = acc[mt][nt][2] + b0, v3 = acc[mt][nt][3] + b1;
            if (EPI == 0) {
                float2 p0 = {v0, v1}, p1 = {v2, v3};
                *(float2*)&Cf[(size_t)row0 * N + col] = p0;
                *(float2*)&Cf[(size_t)(row0 + 8) * N + col] = p1;
            } else {
                v0 = 0.5f * v0 * (1.0f + erff(v0 * 0.7071067811865475f));
                v1 = 0.5f * v1 * (1.0f + erff(v1 * 0.7071067811865475f));
                v2 = 0.5f * v2 * (1.0f + erff(v2 * 0.7071067811865475f));
                v3 = 0.5f * v3 * (1.0f + erff(v3 * 0.7071067811865475f));
                __nv_bfloat162 hh, ll;
                hh.x = __float2bfloat16(v0); hh.y = __float2bfloat16(v1);
                ll.x = __float2bfloat16(v0 - __bfloat162float(hh.x));
                ll.y = __float2bfloat16(v1 - __bfloat162float(hh.y));
                *(__nv_bfloat162*)&Chi[(size_t)row0 * N + col] = hh;
                *(__nv_bfloat162*)&Clo[(size_t)row0 * N + col] = ll;
                hh.x = __float2bfloat16(v2); hh.y = __float2bfloat16(v3);
                ll.x = __float2bfloat16(v2 - __bfloat162float(hh.x));
                ll.y = __float2bfloat16(v3 - __bfloat162float(hh.y));
                *(__nv_bfloat162*)&Chi[(size_t)(row0 + 8) * N + col] = hh;
                *(__nv_bfloat162*)&Clo[(size_t)(row0 + 8) * N + col] = ll;
            }
        }
    }
}

// ---------------------------------------------------------------------------
// fused attention: grid (5 q-tiles, 256 bh), 8 rows per warp.
// ---------------------------------------------------------------------------
__global__ __launch_bounds__(256) void attn_kernel(int use_prev, int wr)
{
    __shared__ float Ks[TOTAL_S][17];
    __shared__ float Vs[TOTAL_S][17];
    __shared__ float Qs[64][17];

    int bh = blockIdx.y;
    int bc = bh >> 4, h = bh & 15;
    int q0 = blockIdx.x * 64;

    int tid = threadIdx.x;
    for (int i = tid; i < TOTAL_S * DK; i += 256) {
        int s = i >> 4, d = i & 15;
        size_t gi = (size_t)(bc * TOTAL_S + s) * 768 + (h << 4) + d;
        Ks[s][d] = g_qkv[gi + 256];
        Vs[s][d] = g_qkv[gi + 512];
    }
    for (int i = tid; i < 64 * DK; i += 256) {
        int s = i >> 4, d = i & 15;
        Qs[s][d] = g_qkv[(size_t)(bc * TOTAL_S + q0 + s) * 768 + (h << 4) + d];
    }
    __syncthreads();

    int warp = tid >> 5, lane = tid & 31;
    for (int it = 0; it < 8; it++) {
        int qr = warp * 8 + it;
        int qi = q0 + qr;
        float qv[DK];
#pragma unroll
        for (int d = 0; d < DK; d++) qv[d] = Qs[qr][d];

        float* srow = &g_scores[((size_t)bh * TOTAL_S + qi) * TOTAL_S];
        float sc[10];
#pragma unroll
        for (int j = 0; j < 10; j++) {
            int kk = j * 32 + lane;
            float acc = 0.f;
#pragma unroll
            for (int d = 0; d < DK; d++) acc += qv[d] * Ks[kk][d];
            acc *= ATTN_SCALE;
            if (use_prev) acc += srow[kk];
            sc[j] = acc;
            if (wr) srow[kk] = acc;
        }
        float m = sc[0];
#pragma unroll
        for (int j = 1; j < 10; j++) m = fmaxf(m, sc[j]);
#pragma unroll
        for (int o = 16; o; o >>= 1) m = fmaxf(m, __shfl_xor_sync(0xffffffffu, m, o));
        float sum = 0.f;
#pragma unroll
        for (int j = 0; j < 10; j++) { sc[j] = __expf(sc[j] - m); sum += sc[j]; }
#pragma unroll
        for (int o = 16; o; o >>= 1) sum += __shfl_xor_sync(0xffffffffu, sum, o);
        float inv = 1.f / sum;

        float oacc[DK];
#pragma unroll
        for (int d = 0; d < DK; d++) oacc[d] = 0.f;
#pragma unroll
        for (int j = 0; j < 10; j++) {
            int kk = j * 32 + lane;
            float wgt = sc[j] * inv;
#pragma unroll
            for (int d = 0; d < DK; d++) oacc[d] += wgt * Vs[kk][d];
        }
#pragma unroll
        for (int d = 0; d < DK; d++) {
#pragma unroll
            for (int o = 16; o; o >>= 1)
                oacc[d] += __shfl_xor_sync(0xffffffffu, oacc[d], o);
        }
        if (lane < DK) {
            float val = oacc[lane];
            size_t oi = (size_t)(bc * TOTAL_S + qi) * D_MODEL + (h << 4) + lane;
            __nv_bfloat16 hh = __float2bfloat16(val);
            g_o_hi[oi] = hh;
            g_o_lo[oi] = __float2bfloat16(val - __bfloat162float(hh));
        }
    }
}

// ---------------------------------------------------------------------------
__global__ __launch_bounds__(256) void resid_ln_kernel(
    const float* __restrict__ delta,
    const float* __restrict__ gs, const float* __restrict__ gb)
{
    int row = blockIdx.x;
    int d = threadIdx.x;
    int warp = d >> 5, lane = d & 31;
    size_t idx = (size_t)row * D_MODEL + d;
    float t = g_u[idx] + delta[idx];

    __shared__ float sred[8];
    float ws = t;
#pragma unroll
    for (int o = 16; o; o >>= 1) ws += __shfl_xor_sync(0xffffffffu, ws, o);
    if (lane == 0) sred[warp] = ws;
    __syncthreads();
    float tot = 0.f;
#pragma unroll
    for (int i = 0; i < 8; i++) tot += sred[i];
    float mean = tot * (1.0f / D_MODEL);
    __syncthreads();

    float df = t - mean;
    ws = df * df;
#pragma unroll
    for (int o = 16; o; o >>= 1) ws += __shfl_xor_sync(0xffffffffu, ws, o);
    if (lane == 0) sred[warp] = ws;
    __syncthreads();
    tot = 0.f;
#pragma unroll
    for (int i = 0; i < 8; i++) tot += sred[i];
    float var = tot * (1.0f / D_MODEL);

    float y = df * rsqrtf(var + LN_EPS) * gs[d] + gb[d];
    g_u[idx] = y;
    __nv_bfloat16 h = __float2bfloat16(y);
    g_u_hi[idx] = h;
    g_u_lo[idx] = __float2bfloat16(y - __bfloat162float(h));
}

// ---------------------------------------------------------------------------
__global__ __launch_bounds__(96) void head_partial_kernel(const float* __restrict__ Wh)
{
    int d = blockIdx.x;
    int t = threadIdx.x;
    __shared__ float usm[BROWS][TOTAL_S];
    for (int i = t; i < BROWS * TOTAL_S; i += 96) {
        int bcc = i / TOTAL_S, s = i % TOTAL_S;
        usm[bcc][s] = g_u[(size_t)(bcc * TOTAL_S + s) * D_MODEL + d];
    }
    __syncthreads();
    float acc[BROWS];
#pragma unroll
    for (int b = 0; b < BROWS; b++) acc[b] = 0.f;
    for (int s = 0; s < TOTAL_S; s++) {
        float w = Wh[((size_t)d * TOTAL_S + s) * TGT + t];
#pragma unroll
        for (int b = 0; b < BROWS; b++) acc[b] += usm[b][s] * w;
    }
#pragma unroll
    for (int b = 0; b < BROWS; b++)
        g_part[((size_t)d * BROWS + b) * TGT + t] = acc[b];
}

__global__ __launch_bounds__(256) void head_reduce_kernel(
    const float* __restrict__ bh,
    const float* __restrict__ revin_w, const float* __restrict__ revin_b,
    float* __restrict__ out)
{
    int idx = blockIdx.x * blockDim.x + threadIdx.x;
    if (idx >= BROWS * TGT) return;
    int bcc = idx / TGT, t = idx % TGT;
    float acc = 0.f;
    for (int d = 0; d < D_MODEL; d++)
        acc += g_part[((size_t)d * BROWS + bcc) * TGT + t];
    acc += bh[t];
    int c = bcc & 7;
    out[idx] = (acc - revin_b[c]) / (revin_w[c] + 1e-10f) * g_std[bcc] + g_mean[bcc];
}

// ---------------------------------------------------------------------------
extern "C" void kernel_launch(void* const* d_in, const int* in_sizes, int n_in,
                              void* d_out, int out_size)
{
    const float* z       = (const float*)d_in[0];
    const float* revin_w = (const float*)d_in[1];
    const float* revin_b = (const float*)d_in[2];
    const float* Wf      = (const float*)d_in[3];
    const float* bf      = (const float*)d_in[4];
    const float* Wc      = (const float*)d_in[5];
    const float* bcoarse = (const float*)d_in[6];
    const float* Wpos    = (const float*)d_in[7];
    const float* WQ      = (const float*)d_in[8];
    const float* bQ      = (const float*)d_in[9];
    const float* WK      = (const float*)d_in[10];
    const float* bK      = (const float*)d_in[11];
    const float* WV      = (const float*)d_in[12];
    const float* bV      = (const float*)d_in[13];
    const float* WO      = (const float*)d_in[14];
    const float* bO      = (const float*)d_in[15];
    const float* ln1_s   = (const float*)d_in[16];
    const float* ln1_b   = (const float*)d_in[17];
    const float* ln2_s   = (const float*)d_in[18];
    const float* ln2_b   = (const float*)d_in[19];
    const float* F1      = (const float*)d_in[20];
    const float* c1      = (const float*)d_in[21];
    const float* F2      = (const float*)d_in[22];
    const float* c2      = (const float*)d_in[23];
    const float* Wh      = (const float*)d_in[24];
    const float* bh      = (const float*)d_in[25];
    float* out = (float*)d_out;

    float *u, *qkv, *tmp, *bqkv;
    __nv_bfloat16 *uh, *ul, *oh, *ol, *h1h, *h1l, *wth, *wtl;
    cudaGetSymbolAddress((void**)&u,    g_u);
    cudaGetSymbolAddress((void**)&qkv,  g_qkv);
    cudaGetSymbolAddress((void**)&tmp,  g_tmp);
    cudaGetSymbolAddress((void**)&bqkv, g_bqkv);
    cudaGetSymbolAddress((void**)&uh,   g_u_hi);
    cudaGetSymbolAddress((void**)&ul,   g_u_lo);
    cudaGetSymbolAddress((void**)&oh,   g_o_hi);
    cudaGetSymbolAddress((void**)&ol,   g_o_lo);
    cudaGetSymbolAddress((void**)&h1h,  g_h1_hi);
    cudaGetSymbolAddress((void**)&h1l,  g_h1_lo);
    cudaGetSymbolAddress((void**)&wth,  g_wt_hi);
    cudaGetSymbolAddress((void**)&wtl,  g_wt_lo);

    const int SMEM128 = 2 * (2 * 128 * RSTRIDE + 2 * 128 * RSTRIDE);  // 81920
    const int SMEM64  = 2 * (2 * 64  * RSTRIDE + 2 * 128 * RSTRIDE);  // 61440
    cudaFuncSetAttribute(gemm_tc<0,128>, cudaFuncAttributeMaxDynamicSharedMemorySize, SMEM128);
    cudaFuncSetAttribute(gemm_tc<1,128>, cudaFuncAttributeMaxDynamicSharedMemorySize, SMEM128);
    cudaFuncSetAttribute(gemm_tc<0,64>,  cudaFuncAttributeMaxDynamicSharedMemorySize, SMEM64);

    // launch order: 0 wsplit+bias, 1 stats, 2 embed, 3 QKV gemm (profiled slot)
    wsplit_all_kernel<<<dim3(256, 7, NLAYERS), 256>>>(WQ, WK, WV, WO, F1, F2,
                                                      bQ, bK, bV);
    stats_kernel<<<BROWS, 256>>>(z);
    embed_kernel<<<dim3(TOTAL_S, BROWS), 256>>>(z, revin_w, revin_b,
                                                Wf, bf, Wc, bcoarse, Wpos);

    for (int l = 0; l < NLAYERS; l++) {
        const size_t L = (size_t)l * WSTRIDE;
        gemm_tc<0,128><<<dim3(6, 40), 256, SMEM128>>>(
            uh, ul, wth + L + WOFF_Q, wtl + L + WOFF_Q,
            bqkv + l * 768, qkv, nullptr, nullptr, 768, D_MODEL);
        attn_kernel<<<dim3(5, BROWS * NHEADS), 256>>>(l > 0 ? 1 : 0,
                                                      l < NLAYERS - 1 ? 1 : 0);
        gemm_tc<0,64><<<dim3(2, 80), 256, SMEM64>>>(
            oh, ol, wth + L + WOFF_O, wtl + L + WOFF_O,
            bO + l * D_MODEL, tmp, nullptr, nullptr, D_MODEL, D_MODEL);
        resid_ln_kernel<<<SEQ, 256>>>(tmp, ln1_s + l * D_MODEL, ln1_b + l * D_MODEL);
        gemm_tc<1,128><<<dim3(8, 40), 256, SMEM128>>>(
            uh, ul, wth + L + WOFF_F1, wtl + L + WOFF_F1,
            c1 + l * DFF, nullptr, h1h, h1l, DFF, D_MODEL);
        gemm_tc<0,64><<<dim3(2, 80), 256, SMEM64>>>(
            h1h, h1l, wth + L + WOFF_F2, wtl + L + WOFF_F2,
            c2 + l * D_MODEL, tmp, nullptr, nullptr, D_MODEL, DFF);
        resid_ln_kernel<<<SEQ, 256>>>(tmp, ln2_s + l * D_MODEL, ln2_b + l * D_MODEL);
    }

    head_partial_kernel<<<D_MODEL, 96>>>(Wh);
    head_reduce_kernel<<<6, 256>>>(bh, revin_w, revin_b, out);
}

// round 8
// speedup vs baseline: 1.1399x; 1.1399x over previous
#include <cuda_runtime.h>
#include <cuda_bf16.h>
#include <math.h>
#include <stdint.h>

#define CTX      1024
#define BROWS    16
#define TOTAL_S  320
#define NF       256
#define D_MODEL  256
#define NHEADS   16
#define DK       16
#define DFF      1024
#define NLAYERS  4
#define TGT      96
#define SEQ      (BROWS * TOTAL_S)   // 5120
#define ATTN_SCALE 0.25f
#define LN_EPS   1e-5f

// ---------------------------------------------------------------------------
// warp MMA + cp.async helpers (sm_80+ path; tcgen05 unavailable at sm_103)
// ---------------------------------------------------------------------------
__device__ __forceinline__ uint32_t smem_u32(const void* p) {
    uint32_t a;
    asm("{ .reg .u64 t; cvta.to.shared.u64 t, %1; cvt.u32.u64 %0, t; }"
        : "=r"(a) : "l"(p));
    return a;
}
__device__ __forceinline__ void ldsm_x4(uint32_t& r0, uint32_t& r1,
                                        uint32_t& r2, uint32_t& r3, uint32_t addr) {
    asm volatile("ldmatrix.sync.aligned.m8n8.x4.shared.b16 {%0,%1,%2,%3}, [%4];"
                 : "=r"(r0), "=r"(r1), "=r"(r2), "=r"(r3) : "r"(addr));
}
__device__ __forceinline__ void mma_bf16(float* c, const uint32_t* a, const uint32_t* b) {
    asm volatile(
        "mma.sync.aligned.m16n8k16.row.col.f32.bf16.bf16.f32 "
        "{%0,%1,%2,%3}, {%4,%5,%6,%7}, {%8,%9}, {%0,%1,%2,%3};"
        : "+f"(c[0]), "+f"(c[1]), "+f"(c[2]), "+f"(c[3])
        : "r"(a[0]), "r"(a[1]), "r"(a[2]), "r"(a[3]), "r"(b[0]), "r"(b[1]));
}
#define CP_ASYNC16(dst, src) \
    asm volatile("cp.async.cg.shared.global [%0], [%1], 16;" :: "r"(dst), "l"(src))
#define CP_COMMIT() asm volatile("cp.async.commit_group;" ::: "memory")
#define CP_WAIT0()  asm volatile("cp.async.wait_group 0;" ::: "memory")

// ---------------------------------------------------------------------------
// scratch
// ---------------------------------------------------------------------------
__device__ __align__(256) float g_u[SEQ * D_MODEL];
__device__ __align__(256) float g_qkv[SEQ * 768];
__device__ __align__(256) float g_tmp[SEQ * D_MODEL];
__device__ __align__(256) float g_scores[BROWS * NHEADS * TOTAL_S * TOTAL_S];
__device__ float g_mean[BROWS];
__device__ float g_std[BROWS];
__device__ __align__(256) float g_part[D_MODEL * BROWS * TGT];
__device__ __align__(256) float g_bqkv[NLAYERS * 768];

__device__ __align__(256) __nv_bfloat16 g_u_hi[SEQ * D_MODEL];
__device__ __align__(256) __nv_bfloat16 g_u_lo[SEQ * D_MODEL];
__device__ __align__(256) __nv_bfloat16 g_o_hi[SEQ * D_MODEL];
__device__ __align__(256) __nv_bfloat16 g_o_lo[SEQ * D_MODEL];
__device__ __align__(256) __nv_bfloat16 g_h1_hi[SEQ * DFF];
__device__ __align__(256) __nv_bfloat16 g_h1_lo[SEQ * DFF];
#define WOFF_Q   0
#define WOFF_K   65536
#define WOFF_V   131072
#define WOFF_O   196608
#define WOFF_F1  262144
#define WOFF_F2  524288
#define WSTRIDE  786432
__device__ __align__(256) __nv_bfloat16 g_wt_hi[NLAYERS * WSTRIDE];
__device__ __align__(256) __nv_bfloat16 g_wt_lo[NLAYERS * WSTRIDE];

// ---------------------------------------------------------------------------
// merged preprocessing: weight transpose/split, bias pack, RevIN stats
// grid: (256 tiles, 8 kinds, 4 layers); kind 6 = bias pack, kind 7 = stats
// ---------------------------------------------------------------------------
__global__ __launch_bounds__(256) void wsplit_all_kernel(
    const float* __restrict__ WQ, const float* __restrict__ WK,
    const float* __restrict__ WV, const float* __restrict__ WO,
    const float* __restrict__ F1, const float* __restrict__ F2,
    const float* __restrict__ bQ, const float* __restrict__ bK,
    const float* __restrict__ bV, const float* __restrict__ z)
{
    int kind = blockIdx.y, l = blockIdx.z, tile = blockIdx.x;
    __shared__ float t[32][33];

    if (kind == 6) {
        if (tile >= 3) return;
        int i = tile * 256 + threadIdx.x;
        if (i >= 768) return;
        float v = (i < 256) ? bQ[l * 256 + i]
                : (i < 512) ? bK[l * 256 + i - 256]
                            : bV[l * 256 + i - 512];
        g_bqkv[l * 768 + i] = v;
        return;
    }
    if (kind == 7) {
        if (l != 0 || tile >= BROWS) return;
        int r = tile, tid = threadIdx.x;
        float s = 0.f, s2 = 0.f;
        for (int i = tid; i < CTX; i += 256) {
            float v = z[r * CTX + i];
            s += v; s2 += v * v;
        }
        float* rs = &t[0][0];
        float* rq = rs + 256;
        rs[tid] = s; rq[tid] = s2;
        __syncthreads();
        for (int o = 128; o; o >>= 1) {
            if (tid < o) { rs[tid] += rs[tid + o]; rq[tid] += rq[tid + o]; }
            __syncthreads();
        }
        if (tid == 0) {
            float m = rs[0] / CTX;
            float var = rq[0] / CTX - m * m;
            g_mean[r] = m;
            g_std[r]  = sqrtf(var + LN_EPS);
        }
        return;
    }

    const float* W; int R, C; size_t inl, ooff;
    switch (kind) {
        case 0: W = WQ; R = 256;  C = 256;  inl = 65536;  ooff = WOFF_Q;  break;
        case 1: W = WK; R = 256;  C = 256;  inl = 65536;  ooff = WOFF_K;  break;
        case 2: W = WV; R = 256;  C = 256;  inl = 65536;  ooff = WOFF_V;  break;
        case 3: W = WO; R = 256;  C = 256;  inl = 65536;  ooff = WOFF_O;  break;
        case 4: W = F1; R = 256;  C = 1024; inl = 262144; ooff = WOFF_F1; break;
        default: W = F2; R = 1024; C = 256; inl = 262144; ooff = WOFF_F2; break;
    }
    int ct = C >> 5, rt = R >> 5;
    if (tile >= ct * rt) return;
    int c0 = (tile % ct) << 5, r0 = (tile / ct) << 5;
    const float* Wl = W + (size_t)l * inl;

    int tx = threadIdx.x & 31, ty = threadIdx.x >> 5;
#pragma unroll
    for (int i = 0; i < 32; i += 8)
        t[ty + i][tx] = Wl[(size_t)(r0 + ty + i) * C + c0 + tx];
    __syncthreads();
#pragma unroll
    for (int i = 0; i < 32; i += 8) {
        float x = t[tx][ty + i];
        size_t oi = (size_t)l * WSTRIDE + ooff + (size_t)(c0 + ty + i) * R + (r0 + tx);
        __nv_bfloat16 h = __float2bfloat16(x);
        g_wt_hi[oi] = h;
        g_wt_lo[oi] = __float2bfloat16(x - __bfloat162float(h));
    }
}

// ---------------------------------------------------------------------------
__global__ __launch_bounds__(256) void embed_kernel(
    const float* __restrict__ z,
    const float* __restrict__ revin_w, const float* __restrict__ revin_b,
    const float* __restrict__ Wf, const float* __restrict__ bf,
    const float* __restrict__ Wc, const float* __restrict__ bcoarse,
    const float* __restrict__ Wpos)
{
    int bch = blockIdx.y;
    int s   = blockIdx.x;
    int d   = threadIdx.x;
    int c   = bch & 7;

    __shared__ float patch[32];
    int plen, stride, p;
    const float* W; const float* bias;
    if (s < NF) { plen = 8;  stride = 4;  p = s;      W = Wf; bias = bf; }
    else        { plen = 32; stride = 16; p = s - NF; W = Wc; bias = bcoarse; }

    if (d < plen) {
        int t = p * stride + d;
        if (t > CTX - 1) t = CTX - 1;
        float zv = z[bch * CTX + t];
        patch[d] = (zv - g_mean[bch]) / g_std[bch] * revin_w[c] + revin_b[c];
    }
    __syncthreads();

    float acc = bias[d] + Wpos[s * D_MODEL + d];
    for (int i = 0; i < plen; i++) acc += patch[i] * W[i * D_MODEL + d];
    size_t idx = (size_t)(bch * TOTAL_S + s) * D_MODEL + d;
    g_u[idx] = acc;
    __nv_bfloat16 h = __float2bfloat16(acc);
    g_u_hi[idx] = h;
    g_u_lo[idx] = __float2bfloat16(acc - __bfloat162float(h));
}

// ---------------------------------------------------------------------------
// HMMA bf16x3 GEMM, cp.async 2-stage pipeline, K-chunk 64 (R6 config).
// ---------------------------------------------------------------------------
#define ASTRIDE 72

template<int EPI, int MT>
__global__ __launch_bounds__(256) void gemm_tc(
    const __nv_bfloat16* __restrict__ Ah, const __nv_bfloat16* __restrict__ Al,
    const __nv_bfloat16* __restrict__ Bh, const __nv_bfloat16* __restrict__ Bl,
    const float* __restrict__ bias,
    float* __restrict__ Cf,
    __nv_bfloat16* __restrict__ Chi, __nv_bfloat16* __restrict__ Clo,
    int N, int K)
{
    constexpr int WNs = (MT == 128) ? 2 : 4;
    constexpr int NT  = 16 / WNs;
    constexpr int BUF_A = MT * ASTRIDE * 2;
    constexpr int BUF_B = 128 * ASTRIDE * 2;
    constexpr int STAGE = 2 * BUF_A + 2 * BUF_B;

    extern __shared__ char smem[];
    const uint32_t sbase = smem_u32(smem);

    const int tid = threadIdx.x;
    const int bm = blockIdx.y * MT, bn = blockIdx.x * 128;
    const int warp = tid >> 5, lane = tid & 31;
    const int wm = warp / WNs, wn = warp % WNs;

    const int sr = tid >> 3, sc = (tid & 7) * 8;

    float acc[2][NT][4];
#pragma unroll
    for (int mt = 0; mt < 2; mt++)
#pragma unroll
        for (int nt = 0; nt < NT; nt++)
#pragma unroll
            for (int i = 0; i < 4; i++) acc[mt][nt][i] = 0.f;

    const int gg = lane >> 3, l7 = lane & 7;
    const int a_row = (gg & 1) * 8 + l7;
    const int a_kb  = (gg >> 1) * 16;
    const int b_row = (gg >> 1) * 8 + l7;
    const int b_kb  = (gg & 1) * 16;

    const int nchunk = K >> 6;

#define STAGE_LOAD(kc, s) do { \
        const int _k0 = (kc) << 6; \
        uint32_t _base = sbase + (s) * STAGE; \
        _Pragma("unroll") \
        for (int i = 0; i < MT / 32; i++) { \
            int r = sr + i * 32; \
            uint32_t so = _base + r * 144 + sc * 2; \
            CP_ASYNC16(so, Ah + (size_t)(bm + r) * K + _k0 + sc); \
            CP_ASYNC16(so + BUF_A, Al + (size_t)(bm + r) * K + _k0 + sc); \
        } \
        _Pragma("unroll") \
        for (int i = 0; i < 4; i++) { \
            int r = sr + i * 32; \
            uint32_t so = _base + 2 * BUF_A + r * 144 + sc * 2; \
            CP_ASYNC16(so, Bh + (size_t)(bn + r) * K + _k0 + sc); \
            CP_ASYNC16(so + BUF_B, Bl + (size_t)(bn + r) * K + _k0 + sc); \
        } \
        CP_COMMIT(); \
    } while (0)

    STAGE_LOAD(0, 0);

    for (int kc = 0; kc < nchunk; kc++) {
        CP_WAIT0();
        __syncthreads();
        if (kc + 1 < nchunk) STAGE_LOAD(kc + 1, (kc + 1) & 1);

        const uint32_t base = sbase + (kc & 1) * STAGE;
        const uint32_t uAh = base, uAl = base + BUF_A;
        const uint32_t uBh = base + 2 * BUF_A, uBl = uBh + BUF_B;

#pragma unroll
        for (int ks = 0; ks < 4; ks++) {
            uint32_t ah[2][4], al[2][4], bh[NT][2], bl[NT][2];
#pragma unroll
            for (int mt = 0; mt < 2; mt++) {
                int row = wm * 32 + mt * 16 + a_row;
                uint32_t off = (uint32_t)(row * 144 + ks * 32 + a_kb);
                ldsm_x4(ah[mt][0], ah[mt][1], ah[mt][2], ah[mt][3], uAh + off);
                ldsm_x4(al[mt][0], al[mt][1], al[mt][2], al[mt][3], uAl + off);
            }
#pragma unroll
            for (int j = 0; j < NT / 2; j++) {
                int row = wn * (128 / WNs) + j * 16 + b_row;
                uint32_t off = (uint32_t)(row * 144 + ks * 32 + b_kb);
                uint32_t r0, r1, r2, r3;
                ldsm_x4(r0, r1, r2, r3, uBh + off);
                bh[2 * j][0] = r0; bh[2 * j][1] = r1;
                bh[2 * j + 1][0] = r2; bh[2 * j + 1][1] = r3;
                ldsm_x4(r0, r1, r2, r3, uBl + off);
                bl[2 * j][0] = r0; bl[2 * j][1] = r1;
                bl[2 * j + 1][0] = r2; bl[2 * j + 1][1] = r3;
            }
#pragma unroll
            for (int mt = 0; mt < 2; mt++)
#pragma unroll
                for (int nt = 0; nt < NT; nt++) {
                    mma_bf16(acc[mt][nt], ah[mt], bh[nt]);
                    mma_bf16(acc[mt][nt], ah[mt], bl[nt]);
                    mma_bf16(acc[mt][nt], al[mt], bh[nt]);
                }
        }
        __syncthreads();
    }
#undef STAGE_LOAD

#pragma unroll
    for (int mt = 0; mt < 2; mt++) {
        int row0 = bm + wm * 32 + mt * 16 + (lane >> 2);
#pragma unroll
        for (int nt = 0; nt < NT; nt++) {
            int col = bn + wn * (128 / WNs) + nt * 8 + (lane & 3) * 2;
            float b0 = bias[col], b1 = bias[col + 1];
            float v0 = acc[mt][nt][0] + b0, v1 = acc[mt][nt][1] + b1;
            float v2 = acc[mt][nt][2] + b0, v3 = acc[mt][nt][3] + b1;
            if (EPI == 0) {
                float2 p0 = {v0, v1}, p1 = {v2, v3};
                *(float2*)&Cf[(size_t)row0 * N + col] = p0;
                *(float2*)&Cf[(size_t)(row0 + 8) * N + col] = p1;
            } else {
                v0 = 0.5f * v0 * (1.0f + erff(v0 * 0.7071067811865475f));
                v1 = 0.5f * v1 * (1.0f + erff(v1 * 0.7071067811865475f));
                v2 = 0.5f * v2 * (1.0f + erff(v2 * 0.7071067811865475f));
                v3 = 0.5f * v3 * (1.0f + erff(v3 * 0.7071067811865475f));
                __nv_bfloat162 hh, ll;
                hh.x = __float2bfloat16(v0); hh.y = __float2bfloat16(v1);
                ll.x = __float2bfloat16(v0 - __bfloat162float(hh.x));
                ll.y = __float2bfloat16(v1 - __bfloat162float(hh.y));
                *(__nv_bfloat162*)&Chi[(size_t)row0 * N + col] = hh;
                *(__nv_bfloat162*)&Clo[(size_t)row0 * N + col] = ll;
                hh.x = __float2bfloat16(v2); hh.y = __float2bfloat16(v3);
                ll.x = __float2bfloat16(v2 - __bfloat162float(hh.x));
                ll.y = __float2bfloat16(v3 - __bfloat162float(hh.y));
                *(__nv_bfloat162*)&Chi[(size_t)(row0 + 8) * N + col] = hh;
                *(__nv_bfloat162*)&Clo[(size_t)(row0 + 8) * N + col] = ll;
            }
        }
    }
}

// ---------------------------------------------------------------------------
// fused attention: grid (5 q-tiles, 256 bh); row-pair register tiling —
// each K/V smem value loaded once per 2 q-rows (halves LDS traffic).
// ---------------------------------------------------------------------------
__global__ __launch_bounds__(256) void attn_kernel(int use_prev, int wr)
{
    __shared__ float Ks[TOTAL_S][17];
    __shared__ float Vs[TOTAL_S][17];
    __shared__ float Qs[64][17];

    int bh = blockIdx.y;
    int bc = bh >> 4, h = bh & 15;
    int q0 = blockIdx.x * 64;

    int tid = threadIdx.x;
    for (int i = tid; i < TOTAL_S * DK; i += 256) {
        int s = i >> 4, d = i & 15;
        size_t gi = (size_t)(bc * TOTAL_S + s) * 768 + (h << 4) + d;
        Ks[s][d] = g_qkv[gi + 256];
        Vs[s][d] = g_qkv[gi + 512];
    }
    for (int i = tid; i < 64 * DK; i += 256) {
        int s = i >> 4, d = i & 15;
        Qs[s][d] = g_qkv[(size_t)(bc * TOTAL_S + q0 + s) * 768 + (h << 4) + d];
    }
    __syncthreads();

    int warp = tid >> 5, lane = tid & 31;
#pragma unroll 1
    for (int pr = 0; pr < 4; pr++) {
        int qra = warp * 8 + pr * 2;
        int qrb = qra + 1;
        float qa[DK], qb[DK];
#pragma unroll
        for (int d = 0; d < DK; d++) { qa[d] = Qs[qra][d]; qb[d] = Qs[qrb][d]; }

        float* sra = &g_scores[((size_t)bh * TOTAL_S + q0 + qra) * TOTAL_S];
        float* srb = sra + TOTAL_S;
        float sa[10], sb[10];
#pragma unroll
        for (int j = 0; j < 10; j++) {
            int kk = j * 32 + lane;
            float aa = 0.f, ab = 0.f;
#pragma unroll
            for (int d = 0; d < DK; d++) {
                float kv = Ks[kk][d];
                aa += qa[d] * kv;
                ab += qb[d] * kv;
            }
            aa *= ATTN_SCALE; ab *= ATTN_SCALE;
            if (use_prev) { aa += sra[kk]; ab += srb[kk]; }
            sa[j] = aa; sb[j] = ab;
            if (wr) { sra[kk] = aa; srb[kk] = ab; }
        }
        float ma = sa[0], mb = sb[0];
#pragma unroll
        for (int j = 1; j < 10; j++) { ma = fmaxf(ma, sa[j]); mb = fmaxf(mb, sb[j]); }
#pragma unroll
        for (int o = 16; o; o >>= 1) {
            ma = fmaxf(ma, __shfl_xor_sync(0xffffffffu, ma, o));
            mb = fmaxf(mb, __shfl_xor_sync(0xffffffffu, mb, o));
        }
        float suma = 0.f, sumb = 0.f;
#pragma unroll
        for (int j = 0; j < 10; j++) {
            sa[j] = __expf(sa[j] - ma); suma += sa[j];
            sb[j] = __expf(sb[j] - mb); sumb += sb[j];
        }
#pragma unroll
        for (int o = 16; o; o >>= 1) {
            suma += __shfl_xor_sync(0xffffffffu, suma, o);
            sumb += __shfl_xor_sync(0xffffffffu, sumb, o);
        }
        float inva = 1.f / suma, invb = 1.f / sumb;

        float oa[DK], ob[DK];
#pragma unroll
        for (int d = 0; d < DK; d++) { oa[d] = 0.f; ob[d] = 0.f; }
#pragma unroll
        for (int j = 0; j < 10; j++) {
            int kk = j * 32 + lane;
            float wa = sa[j] * inva, wb = sb[j] * invb;
#pragma unroll
            for (int d = 0; d < DK; d++) {
                float vv = Vs[kk][d];
                oa[d] += wa * vv;
                ob[d] += wb * vv;
            }
        }
#pragma unroll
        for (int d = 0; d < DK; d++) {
#pragma unroll
            for (int o = 16; o; o >>= 1) {
                oa[d] += __shfl_xor_sync(0xffffffffu, oa[d], o);
                ob[d] += __shfl_xor_sync(0xffffffffu, ob[d], o);
            }
        }
        // lanes 0-15 write row A, lanes 16-31 write row B
        int dsel = lane & 15;
        float val = (lane < 16) ? oa[dsel] : ob[dsel];
        int qi = q0 + ((lane < 16) ? qra : qrb);
        size_t oi = (size_t)(bc * TOTAL_S + qi) * D_MODEL + (h << 4) + dsel;
        __nv_bfloat16 hh = __float2bfloat16(val);
        g_o_hi[oi] = hh;
        g_o_lo[oi] = __float2bfloat16(val - __bfloat162float(hh));
    }
}

// ---------------------------------------------------------------------------
__global__ __launch_bounds__(256) void resid_ln_kernel(
    const float* __restrict__ delta,
    const float* __restrict__ gs, const float* __restrict__ gb)
{
    int row = blockIdx.x;
    int d = threadIdx.x;
    int warp = d >> 5, lane = d & 31;
    size_t idx = (size_t)row * D_MODEL + d;
    float t = g_u[idx] + delta[idx];

    __shared__ float sred[8];
    float ws = t;
#pragma unroll
    for (int o = 16; o; o >>= 1) ws += __shfl_xor_sync(0xffffffffu, ws, o);
    if (lane == 0) sred[warp] = ws;
    __syncthreads();
    float tot = 0.f;
#pragma unroll
    for (int i = 0; i < 8; i++) tot += sred[i];
    float mean = tot * (1.0f / D_MODEL);
    __syncthreads();

    float df = t - mean;
    ws = df * df;
#pragma unroll
    for (int o = 16; o; o >>= 1) ws += __shfl_xor_sync(0xffffffffu, ws, o);
    if (lane == 0) sred[warp] = ws;
    __syncthreads();
    tot = 0.f;
#pragma unroll
    for (int i = 0; i < 8; i++) tot += sred[i];
    float var = tot * (1.0f / D_MODEL);

    float y = df * rsqrtf(var + LN_EPS) * gs[d] + gb[d];
    g_u[idx] = y;
    __nv_bfloat16 h = __float2bfloat16(y);
    g_u_hi[idx] = h;
    g_u_lo[idx] = __float2bfloat16(y - __bfloat162float(h));
}

// ---------------------------------------------------------------------------
__global__ __launch_bounds__(96) void head_partial_kernel(const float* __restrict__ Wh)
{
    int d = blockIdx.x;
    int t = threadIdx.x;
    __shared__ float usm[BROWS][TOTAL_S];
    for (int i = t; i < BROWS * TOTAL_S; i += 96) {
        int bcc = i / TOTAL_S, s = i % TOTAL_S;
        usm[bcc][s] = g_u[(size_t)(bcc * TOTAL_S + s) * D_MODEL + d];
    }
    __syncthreads();
    float acc[BROWS];
#pragma unroll
    for (int b = 0; b < BROWS; b++) acc[b] = 0.f;
    for (int s = 0; s < TOTAL_S; s++) {
        float w = Wh[((size_t)d * TOTAL_S + s) * TGT + t];
#pragma unroll
        for (int b = 0; b < BROWS; b++) acc[b] += usm[b][s] * w;
    }
#pragma unroll
    for (int b = 0; b < BROWS; b++)
        g_part[((size_t)d * BROWS + b) * TGT + t] = acc[b];
}

__global__ __launch_bounds__(256) void head_reduce_kernel(
    const float* __restrict__ bh,
    const float* __restrict__ revin_w, const float* __restrict__ revin_b,
    float* __restrict__ out)
{
    int idx = blockIdx.x * blockDim.x + threadIdx.x;
    if (idx >= BROWS * TGT) return;
    int bcc = idx / TGT, t = idx % TGT;
    float acc = 0.f;
    for (int d = 0; d < D_MODEL; d++)
        acc += g_part[((size_t)d * BROWS + bcc) * TGT + t];
    acc += bh[t];
    int c = bcc & 7;
    out[idx] = (acc - revin_b[c]) / (revin_w[c] + 1e-10f) * g_std[bcc] + g_mean[bcc];
}

// ---------------------------------------------------------------------------
extern "C" void kernel_launch(void* const* d_in, const int* in_sizes, int n_in,
                              void* d_out, int out_size)
{
    const float* z       = (const float*)d_in[0];
    const float* revin_w = (const float*)d_in[1];
    const float* revin_b = (const float*)d_in[2];
    const float* Wf      = (const float*)d_in[3];
    const float* bf      = (const float*)d_in[4];
    const float* Wc      = (const float*)d_in[5];
    const float* bcoarse = (const float*)d_in[6];
    const float* Wpos    = (const float*)d_in[7];
    const float* WQ      = (const float*)d_in[8];
    const float* bQ      = (const float*)d_in[9];
    const float* WK      = (const float*)d_in[10];
    const float* bK      = (const float*)d_in[11];
    const float* WV      = (const float*)d_in[12];
    const float* bV      = (const float*)d_in[13];
    const float* WO      = (const float*)d_in[14];
    const float* bO      = (const float*)d_in[15];
    const float* ln1_s   = (const float*)d_in[16];
    const float* ln1_b   = (const float*)d_in[17];
    const float* ln2_s   = (const float*)d_in[18];
    const float* ln2_b   = (const float*)d_in[19];
    const float* F1      = (const float*)d_in[20];
    const float* c1      = (const float*)d_in[21];
    const float* F2      = (const float*)d_in[22];
    const float* c2      = (const float*)d_in[23];
    const float* Wh      = (const float*)d_in[24];
    const float* bh      = (const float*)d_in[25];
    float* out = (float*)d_out;

    float *u, *qkv, *tmp, *bqkv;
    __nv_bfloat16 *uh, *ul, *oh, *ol, *h1h, *h1l, *wth, *wtl;
    cudaGetSymbolAddress((void**)&u,    g_u);
    cudaGetSymbolAddress((void**)&qkv,  g_qkv);
    cudaGetSymbolAddress((void**)&tmp,  g_tmp);
    cudaGetSymbolAddress((void**)&bqkv, g_bqkv);
    cudaGetSymbolAddress((void**)&uh,   g_u_hi);
    cudaGetSymbolAddress((void**)&ul,   g_u_lo);
    cudaGetSymbolAddress((void**)&oh,   g_o_hi);
    cudaGetSymbolAddress((void**)&ol,   g_o_lo);
    cudaGetSymbolAddress((void**)&h1h,  g_h1_hi);
    cudaGetSymbolAddress((void**)&h1l,  g_h1_lo);
    cudaGetSymbolAddress((void**)&wth,  g_wt_hi);
    cudaGetSymbolAddress((void**)&wtl,  g_wt_lo);

    const int SMEM128 = 2 * (2 * 128 * ASTRIDE * 2 + 2 * 128 * ASTRIDE * 2);
    const int SMEM64  = 2 * (2 * 64  * ASTRIDE * 2 + 2 * 128 * ASTRIDE * 2);
    cudaFuncSetAttribute(gemm_tc<0,128>, cudaFuncAttributeMaxDynamicSharedMemorySize, SMEM128);
    cudaFuncSetAttribute(gemm_tc<1,128>, cudaFuncAttributeMaxDynamicSharedMemorySize, SMEM128);
    cudaFuncSetAttribute(gemm_tc<0,64>,  cudaFuncAttributeMaxDynamicSharedMemorySize, SMEM64);

    // launch order: 0 wsplit(+bias+stats), 1 embed, 2 QKV gemm, 3 attn (profiled)
    wsplit_all_kernel<<<dim3(256, 8, NLAYERS), 256>>>(WQ, WK, WV, WO, F1, F2,
                                                      bQ, bK, bV, z);
    embed_kernel<<<dim3(TOTAL_S, BROWS), 256>>>(z, revin_w, revin_b,
                                                Wf, bf, Wc, bcoarse, Wpos);

    for (int l = 0; l < NLAYERS; l++) {
        const size_t L = (size_t)l * WSTRIDE;
        gemm_tc<0,128><<<dim3(6, 40), 256, SMEM128>>>(
            uh, ul, wth + L + WOFF_Q, wtl + L + WOFF_Q,
            bqkv + l * 768, qkv, nullptr, nullptr, 768, D_MODEL);
        attn_kernel<<<dim3(5, BROWS * NHEADS), 256>>>(l > 0 ? 1 : 0,
                                                      l < NLAYERS - 1 ? 1 : 0);
        gemm_tc<0,64><<<dim3(2, 80), 256, SMEM64>>>(
            oh, ol, wth + L + WOFF_O, wtl + L + WOFF_O,
            bO + l * D_MODEL, tmp, nullptr, nullptr, D_MODEL, D_MODEL);
        resid_ln_kernel<<<SEQ, 256>>>(tmp, ln1_s + l * D_MODEL, ln1_b + l * D_MODEL);
        gemm_tc<1,128><<<dim3(8, 40), 256, SMEM128>>>(
            uh, ul, wth + L + WOFF_F1, wtl + L + WOFF_F1,
            c1 + l * DFF, nullptr, h1h, h1l, DFF, D_MODEL);
        gemm_tc<0,64><<<dim3(2, 80), 256, SMEM64>>>(
            h1h, h1l, wth + L + WOFF_F2, wtl + L + WOFF_F2,
            c2 + l * D_MODEL, tmp, nullptr, nullptr, D_MODEL, DFF);
        resid_ln_kernel<<<SEQ, 256>>>(tmp, ln2_s + l * D_MODEL, ln2_b + l * D_MODEL);
    }

    head_partial_kernel<<<D_MODEL, 96>>>(Wh);
    head_reduce_kernel<<<6, 256>>>(bh, revin_w, revin_b, out);
}

// round 11
// speedup vs baseline: 1.1751x; 1.0309x over previous
#include <cuda_runtime.h>
#include <cuda_bf16.h>
#include <math.h>
#include <stdint.h>

#define CTX      1024
#define BROWS    16
#define TOTAL_S  320
#define NF       256
#define D_MODEL  256
#define NHEADS   16
#define DK       16
#define DFF      1024
#define NLAYERS  4
#define TGT      96
#define SEQ      (BROWS * TOTAL_S)   // 5120
#define ATTN_SCALE 0.25f
#define LN_EPS   1e-5f

// ---------------------------------------------------------------------------
// warp MMA + cp.async helpers (sm_80+ path; tcgen05 unavailable at sm_103)
// ---------------------------------------------------------------------------
__device__ __forceinline__ uint32_t smem_u32(const void* p) {
    uint32_t a;
    asm("{ .reg .u64 t; cvta.to.shared.u64 t, %1; cvt.u32.u64 %0, t; }"
        : "=r"(a) : "l"(p));
    return a;
}
__device__ __forceinline__ void ldsm_x4(uint32_t& r0, uint32_t& r1,
                                        uint32_t& r2, uint32_t& r3, uint32_t addr) {
    asm volatile("ldmatrix.sync.aligned.m8n8.x4.shared.b16 {%0,%1,%2,%3}, [%4];"
                 : "=r"(r0), "=r"(r1), "=r"(r2), "=r"(r3) : "r"(addr));
}
__device__ __forceinline__ void mma_bf16(float* c, const uint32_t* a, const uint32_t* b) {
    asm volatile(
        "mma.sync.aligned.m16n8k16.row.col.f32.bf16.bf16.f32 "
        "{%0,%1,%2,%3}, {%4,%5,%6,%7}, {%8,%9}, {%0,%1,%2,%3};"
        : "+f"(c[0]), "+f"(c[1]), "+f"(c[2]), "+f"(c[3])
        : "r"(a[0]), "r"(a[1]), "r"(a[2]), "r"(a[3]), "r"(b[0]), "r"(b[1]));
}
#define CP_ASYNC16(dst, src) \
    asm volatile("cp.async.cg.shared.global [%0], [%1], 16;" :: "r"(dst), "l"(src))
#define CP_COMMIT() asm volatile("cp.async.commit_group;" ::: "memory")
#define CP_WAIT0()  asm volatile("cp.async.wait_group 0;" ::: "memory")

// ---------------------------------------------------------------------------
// scratch
// ---------------------------------------------------------------------------
__device__ __align__(256) float g_u[SEQ * D_MODEL];
__device__ __align__(256) float g_qkv[SEQ * 768];
__device__ __align__(256) float g_tmp[SEQ * D_MODEL];
__device__ __align__(256) float g_scores[BROWS * NHEADS * TOTAL_S * TOTAL_S];
__device__ float g_mean[BROWS];
__device__ float g_std[BROWS];
__device__ __align__(256) float g_part[D_MODEL * BROWS * TGT];
__device__ __align__(256) float g_bqkv[NLAYERS * 768];

__device__ __align__(256) __nv_bfloat16 g_u_hi[SEQ * D_MODEL];
__device__ __align__(256) __nv_bfloat16 g_u_lo[SEQ * D_MODEL];
__device__ __align__(256) __nv_bfloat16 g_o_hi[SEQ * D_MODEL];
__device__ __align__(256) __nv_bfloat16 g_o_lo[SEQ * D_MODEL];
__device__ __align__(256) __nv_bfloat16 g_h1_hi[SEQ * DFF];
__device__ __align__(256) __nv_bfloat16 g_h1_lo[SEQ * DFF];
#define WOFF_Q   0
#define WOFF_K   65536
#define WOFF_V   131072
#define WOFF_O   196608
#define WOFF_F1  262144
#define WOFF_F2  524288
#define WSTRIDE  786432
__device__ __align__(256) __nv_bfloat16 g_wt_hi[NLAYERS * WSTRIDE];
__device__ __align__(256) __nv_bfloat16 g_wt_lo[NLAYERS * WSTRIDE];

// ---------------------------------------------------------------------------
// merged preprocessing: weight transpose/split, bias pack, RevIN stats
// ---------------------------------------------------------------------------
__global__ __launch_bounds__(256) void wsplit_all_kernel(
    const float* __restrict__ WQ, const float* __restrict__ WK,
    const float* __restrict__ WV, const float* __restrict__ WO,
    const float* __restrict__ F1, const float* __restrict__ F2,
    const float* __restrict__ bQ, const float* __restrict__ bK,
    const float* __restrict__ bV, const float* __restrict__ z)
{
    int kind = blockIdx.y, l = blockIdx.z, tile = blockIdx.x;
    __shared__ float t[32][33];

    if (kind == 6) {
        if (tile >= 3) return;
        int i = tile * 256 + threadIdx.x;
        if (i >= 768) return;
        float v = (i < 256) ? bQ[l * 256 + i]
                : (i < 512) ? bK[l * 256 + i - 256]
                            : bV[l * 256 + i - 512];
        g_bqkv[l * 768 + i] = v;
        return;
    }
    if (kind == 7) {
        if (l != 0 || tile >= BROWS) return;
        int r = tile, tid = threadIdx.x;
        float s = 0.f, s2 = 0.f;
        for (int i = tid; i < CTX; i += 256) {
            float v = z[r * CTX + i];
            s += v; s2 += v * v;
        }
        float* rs = &t[0][0];
        float* rq = rs + 256;
        rs[tid] = s; rq[tid] = s2;
        __syncthreads();
        for (int o = 128; o; o >>= 1) {
            if (tid < o) { rs[tid] += rs[tid + o]; rq[tid] += rq[tid + o]; }
            __syncthreads();
        }
        if (tid == 0) {
            float m = rs[0] / CTX;
            float var = rq[0] / CTX - m * m;
            g_mean[r] = m;
            g_std[r]  = sqrtf(var + LN_EPS);
        }
        return;
    }

    const float* W; int R, C; size_t inl, ooff;
    switch (kind) {
        case 0: W = WQ; R = 256;  C = 256;  inl = 65536;  ooff = WOFF_Q;  break;
        case 1: W = WK; R = 256;  C = 256;  inl = 65536;  ooff = WOFF_K;  break;
        case 2: W = WV; R = 256;  C = 256;  inl = 65536;  ooff = WOFF_V;  break;
        case 3: W = WO; R = 256;  C = 256;  inl = 65536;  ooff = WOFF_O;  break;
        case 4: W = F1; R = 256;  C = 1024; inl = 262144; ooff = WOFF_F1; break;
        default: W = F2; R = 1024; C = 256; inl = 262144; ooff = WOFF_F2; break;
    }
    int ct = C >> 5, rt = R >> 5;
    if (tile >= ct * rt) return;
    int c0 = (tile % ct) << 5, r0 = (tile / ct) << 5;
    const float* Wl = W + (size_t)l * inl;

    int tx = threadIdx.x & 31, ty = threadIdx.x >> 5;
#pragma unroll
    for (int i = 0; i < 32; i += 8)
        t[ty + i][tx] = Wl[(size_t)(r0 + ty + i) * C + c0 + tx];
    __syncthreads();
#pragma unroll
    for (int i = 0; i < 32; i += 8) {
        float x = t[tx][ty + i];
        size_t oi = (size_t)l * WSTRIDE + ooff + (size_t)(c0 + ty + i) * R + (r0 + tx);
        __nv_bfloat16 h = __float2bfloat16(x);
        g_wt_hi[oi] = h;
        g_wt_lo[oi] = __float2bfloat16(x - __bfloat162float(h));
    }
}

// ---------------------------------------------------------------------------
__global__ __launch_bounds__(256) void embed_kernel(
    const float* __restrict__ z,
    const float* __restrict__ revin_w, const float* __restrict__ revin_b,
    const float* __restrict__ Wf, const float* __restrict__ bf,
    const float* __restrict__ Wc, const float* __restrict__ bcoarse,
    const float* __restrict__ Wpos)
{
    int bch = blockIdx.y;
    int s   = blockIdx.x;
    int d   = threadIdx.x;
    int c   = bch & 7;

    __shared__ float patch[32];
    int plen, stride, p;
    const float* W; const float* bias;
    if (s < NF) { plen = 8;  stride = 4;  p = s;      W = Wf; bias = bf; }
    else        { plen = 32; stride = 16; p = s - NF; W = Wc; bias = bcoarse; }

    if (d < plen) {
        int t = p * stride + d;
        if (t > CTX - 1) t = CTX - 1;
        float zv = z[bch * CTX + t];
        patch[d] = (zv - g_mean[bch]) / g_std[bch] * revin_w[c] + revin_b[c];
    }
    __syncthreads();

    float acc = bias[d] + Wpos[s * D_MODEL + d];
    for (int i = 0; i < plen; i++) acc += patch[i] * W[i * D_MODEL + d];
    size_t idx = (size_t)(bch * TOTAL_S + s) * D_MODEL + d;
    g_u[idx] = acc;
    __nv_bfloat16 h = __float2bfloat16(acc);
    g_u_hi[idx] = h;
    g_u_lo[idx] = __float2bfloat16(acc - __bfloat162float(h));
}

// ---------------------------------------------------------------------------
// HMMA bf16x3 GEMM, cp.async 2-stage pipeline, K-chunk 64 (R6 config).
// ---------------------------------------------------------------------------
#define ASTRIDE 72

template<int EPI, int MT>
__global__ __launch_bounds__(256) void gemm_tc(
    const __nv_bfloat16* __restrict__ Ah, const __nv_bfloat16* __restrict__ Al,
    const __nv_bfloat16* __restrict__ Bh, const __nv_bfloat16* __restrict__ Bl,
    const float* __restrict__ bias,
    float* __restrict__ Cf,
    __nv_bfloat16* __restrict__ Chi, __nv_bfloat16* __restrict__ Clo,
    int N, int K)
{
    constexpr int WNs = (MT == 128) ? 2 : 4;
    constexpr int NT  = 16 / WNs;
    constexpr int BUF_A = MT * ASTRIDE * 2;
    constexpr int BUF_B = 128 * ASTRIDE * 2;
    constexpr int STAGE = 2 * BUF_A + 2 * BUF_B;

    extern __shared__ char smem[];
    const uint32_t sbase = smem_u32(smem);

    const int tid = threadIdx.x;
    const int bm = blockIdx.y * MT, bn = blockIdx.x * 128;
    const int warp = tid >> 5, lane = tid & 31;
    const int wm = warp / WNs, wn = warp % WNs;

    const int sr = tid >> 3, sc = (tid & 7) * 8;

    float acc[2][NT][4];
#pragma unroll
    for (int mt = 0; mt < 2; mt++)
#pragma unroll
        for (int nt = 0; nt < NT; nt++)
#pragma unroll
            for (int i = 0; i < 4; i++) acc[mt][nt][i] = 0.f;

    const int gg = lane >> 3, l7 = lane & 7;
    const int a_row = (gg & 1) * 8 + l7;
    const int a_kb  = (gg >> 1) * 16;
    const int b_row = (gg >> 1) * 8 + l7;
    const int b_kb  = (gg & 1) * 16;

    const int nchunk = K >> 6;

#define STAGE_LOAD(kc, s) do { \
        const int _k0 = (kc) << 6; \
        uint32_t _base = sbase + (s) * STAGE; \
        _Pragma("unroll") \
        for (int i = 0; i < MT / 32; i++) { \
            int r = sr + i * 32; \
            uint32_t so = _base + r * 144 + sc * 2; \
            CP_ASYNC16(so, Ah + (size_t)(bm + r) * K + _k0 + sc); \
            CP_ASYNC16(so + BUF_A, Al + (size_t)(bm + r) * K + _k0 + sc); \
        } \
        _Pragma("unroll") \
        for (int i = 0; i < 4; i++) { \
            int r = sr + i * 32; \
            uint32_t so = _base + 2 * BUF_A + r * 144 + sc * 2; \
            CP_ASYNC16(so, Bh + (size_t)(bn + r) * K + _k0 + sc); \
            CP_ASYNC16(so + BUF_B, Bl + (size_t)(bn + r) * K + _k0 + sc); \
        } \
        CP_COMMIT(); \
    } while (0)

    STAGE_LOAD(0, 0);

    for (int kc = 0; kc < nchunk; kc++) {
        CP_WAIT0();
        __syncthreads();
        if (kc + 1 < nchunk) STAGE_LOAD(kc + 1, (kc + 1) & 1);

        const uint32_t base = sbase + (kc & 1) * STAGE;
        const uint32_t uAh = base, uAl = base + BUF_A;
        const uint32_t uBh = base + 2 * BUF_A, uBl = uBh + BUF_B;

#pragma unroll
        for (int ks = 0; ks < 4; ks++) {
            uint32_t ah[2][4], al[2][4], bh[NT][2], bl[NT][2];
#pragma unroll
            for (int mt = 0; mt < 2; mt++) {
                int row = wm * 32 + mt * 16 + a_row;
                uint32_t off = (uint32_t)(row * 144 + ks * 32 + a_kb);
                ldsm_x4(ah[mt][0], ah[mt][1], ah[mt][2], ah[mt][3], uAh + off);
                ldsm_x4(al[mt][0], al[mt][1], al[mt][2], al[mt][3], uAl + off);
            }
#pragma unroll
            for (int j = 0; j < NT / 2; j++) {
                int row = wn * (128 / WNs) + j * 16 + b_row;
                uint32_t off = (uint32_t)(row * 144 + ks * 32 + b_kb);
                uint32_t r0, r1, r2, r3;
                ldsm_x4(r0, r1, r2, r3, uBh + off);
                bh[2 * j][0] = r0; bh[2 * j][1] = r1;
                bh[2 * j + 1][0] = r2; bh[2 * j + 1][1] = r3;
                ldsm_x4(r0, r1, r2, r3, uBl + off);
                bl[2 * j][0] = r0; bl[2 * j][1] = r1;
                bl[2 * j + 1][0] = r2; bl[2 * j + 1][1] = r3;
            }
#pragma unroll
            for (int mt = 0; mt < 2; mt++)
#pragma unroll
                for (int nt = 0; nt < NT; nt++) {
                    mma_bf16(acc[mt][nt], ah[mt], bh[nt]);
                    mma_bf16(acc[mt][nt], ah[mt], bl[nt]);
                    mma_bf16(acc[mt][nt], al[mt], bh[nt]);
                }
        }
        __syncthreads();
    }
#undef STAGE_LOAD

#pragma unroll
    for (int mt = 0; mt < 2; mt++) {
        int row0 = bm + wm * 32 + mt * 16 + (lane >> 2);
#pragma unroll
        for (int nt = 0; nt < NT; nt++) {
            int col = bn + wn * (128 / WNs) + nt * 8 + (lane & 3) * 2;
            float b0 = bias[col], b1 = bias[col + 1];
            float v0 = acc[mt][nt][0] + b0, v1 = acc[mt][nt][1] + b1;
            float v2 = acc[mt][nt][2] + b0, v3 = acc[mt][nt][3] + b1;
            if (EPI == 0) {
                float2 p0 = {v0, v1}, p1 = {v2, v3};
                *(float2*)&Cf[(size_t)row0 * N + col] = p0;
                *(float2*)&Cf[(size_t)(row0 + 8) * N + col] = p1;
            } else {
                v0 = 0.5f * v0 * (1.0f + erff(v0 * 0.7071067811865475f));
                v1 = 0.5f * v1 * (1.0f + erff(v1 * 0.7071067811865475f));
                v2 = 0.5f * v2 * (1.0f + erff(v2 * 0.7071067811865475f));
                v3 = 0.5f * v3 * (1.0f + erff(v3 * 0.7071067811865475f));
                __nv_bfloat162 hh, ll;
                hh.x = __float2bfloat16(v0); hh.y = __float2bfloat16(v1);
                ll.x = __float2bfloat16(v0 - __bfloat162float(hh.x));
                ll.y = __float2bfloat16(v1 - __bfloat162float(hh.y));
                *(__nv_bfloat162*)&Chi[(size_t)row0 * N + col] = hh;
                *(__nv_bfloat162*)&Clo[(size_t)row0 * N + col] = ll;
                hh.x = __float2bfloat16(v2); hh.y = __float2bfloat16(v3);
                ll.x = __float2bfloat16(v2 - __bfloat162float(hh.x));
                ll.y = __float2bfloat16(v3 - __bfloat162float(hh.y));
                *(__nv_bfloat162*)&Chi[(size_t)(row0 + 8) * N + col] = hh;
                *(__nv_bfloat162*)&Clo[(size_t)(row0 + 8) * N + col] = ll;
            }
        }
    }
}

// ---------------------------------------------------------------------------
// fused attention: grid (5 q-tiles, 256 bh); row-pair tiling + float4 smem
// reads (stride 20 floats = 80B rows -> conflict-free LDS.128).
// ---------------------------------------------------------------------------
#define ROWF 20
#define ATTN_SMEM ((TOTAL_S * ROWF * 2 + 64 * ROWF) * 4)   // 56320 B

__global__ __launch_bounds__(256) void attn_kernel(int use_prev, int wr)
{
    extern __shared__ float asm_f[];
    float* Ks = asm_f;                       // [320][20]
    float* Vs = Ks + TOTAL_S * ROWF;
    float* Qs = Vs + TOTAL_S * ROWF;         // [64][20]

    int bh = blockIdx.y;
    int bc = bh >> 4, h = bh & 15;
    int q0 = blockIdx.x * 64;

    int tid = threadIdx.x;
    // stage K/V: 320 rows x 4 float4 chunks
    for (int i = tid; i < TOTAL_S * 4; i += 256) {
        int s = i >> 2, c = i & 3;
        const float4* src = (const float4*)&g_qkv[(size_t)(bc * TOTAL_S + s) * 768 + (h << 4)];
        *(float4*)&Ks[s * ROWF + c * 4] = src[64 + c];   // +256 floats
        *(float4*)&Vs[s * ROWF + c * 4] = src[128 + c];  // +512 floats
    }
    // stage Q tile: 64 rows x 4 chunks = 256 (one pass)
    {
        int s = tid >> 2, c = tid & 3;
        const float4* src = (const float4*)&g_qkv[(size_t)(bc * TOTAL_S + q0 + s) * 768 + (h << 4)];
        *(float4*)&Qs[s * ROWF + c * 4] = src[c];
    }
    __syncthreads();

    int warp = tid >> 5, lane = tid & 31;
#pragma unroll 1
    for (int pr = 0; pr < 4; pr++) {
        int qra = warp * 8 + pr * 2;
        int qrb = qra + 1;
        float qa[DK], qb[DK];
#pragma unroll
        for (int c = 0; c < 4; c++) {
            float4 va = *(float4*)&Qs[qra * ROWF + c * 4];
            float4 vb = *(float4*)&Qs[qrb * ROWF + c * 4];
            qa[c*4+0]=va.x; qa[c*4+1]=va.y; qa[c*4+2]=va.z; qa[c*4+3]=va.w;
            qb[c*4+0]=vb.x; qb[c*4+1]=vb.y; qb[c*4+2]=vb.z; qb[c*4+3]=vb.w;
        }

        float* sra = &g_scores[((size_t)bh * TOTAL_S + q0 + qra) * TOTAL_S];
        float* srb = sra + TOTAL_S;
        float sa[10], sb[10];
#pragma unroll
        for (int j = 0; j < 10; j++) {
            int kk = j * 32 + lane;
            const float4* kp = (const float4*)&Ks[kk * ROWF];
            float aa = 0.f, ab = 0.f;
#pragma unroll
            for (int c = 0; c < 4; c++) {
                float4 kv = kp[c];
                aa += qa[c*4+0]*kv.x + qa[c*4+1]*kv.y + qa[c*4+2]*kv.z + qa[c*4+3]*kv.w;
                ab += qb[c*4+0]*kv.x + qb[c*4+1]*kv.y + qb[c*4+2]*kv.z + qb[c*4+3]*kv.w;
            }
            aa *= ATTN_SCALE; ab *= ATTN_SCALE;
            if (use_prev) { aa += sra[kk]; ab += srb[kk]; }
            sa[j] = aa; sb[j] = ab;
            if (wr) { sra[kk] = aa; srb[kk] = ab; }
        }
        float ma = sa[0], mb = sb[0];
#pragma unroll
        for (int j = 1; j < 10; j++) { ma = fmaxf(ma, sa[j]); mb = fmaxf(mb, sb[j]); }
#pragma unroll
        for (int o = 16; o; o >>= 1) {
            ma = fmaxf(ma, __shfl_xor_sync(0xffffffffu, ma, o));
            mb = fmaxf(mb, __shfl_xor_sync(0xffffffffu, mb, o));
        }
        float suma = 0.f, sumb = 0.f;
#pragma unroll
        for (int j = 0; j < 10; j++) {
            sa[j] = __expf(sa[j] - ma); suma += sa[j];
            sb[j] = __expf(sb[j] - mb); sumb += sb[j];
        }
#pragma unroll
        for (int o = 16; o; o >>= 1) {
            suma += __shfl_xor_sync(0xffffffffu, suma, o);
            sumb += __shfl_xor_sync(0xffffffffu, sumb, o);
        }
        float inva = 1.f / suma, invb = 1.f / sumb;

        float oa[DK], ob[DK];
#pragma unroll
        for (int d = 0; d < DK; d++) { oa[d] = 0.f; ob[d] = 0.f; }
#pragma unroll
        for (int j = 0; j < 10; j++) {
            int kk = j * 32 + lane;
            const float4* vp = (const float4*)&Vs[kk * ROWF];
            float wa = sa[j] * inva, wb = sb[j] * invb;
#pragma unroll
            for (int c = 0; c < 4; c++) {
                float4 vv = vp[c];
                oa[c*4+0] += wa*vv.x; oa[c*4+1] += wa*vv.y;
                oa[c*4+2] += wa*vv.z; oa[c*4+3] += wa*vv.w;
                ob[c*4+0] += wb*vv.x; ob[c*4+1] += wb*vv.y;
                ob[c*4+2] += wb*vv.z; ob[c*4+3] += wb*vv.w;
            }
        }
#pragma unroll
        for (int d = 0; d < DK; d++) {
#pragma unroll
            for (int o = 16; o; o >>= 1) {
                oa[d] += __shfl_xor_sync(0xffffffffu, oa[d], o);
                ob[d] += __shfl_xor_sync(0xffffffffu, ob[d], o);
            }
        }
        int dsel = lane & 15;
        float val = (lane < 16) ? oa[dsel] : ob[dsel];
        int qi = q0 + ((lane < 16) ? qra : qrb);
        size_t oi = (size_t)(bc * TOTAL_S + qi) * D_MODEL + (h << 4) + dsel;
        __nv_bfloat16 hh = __float2bfloat16(val);
        g_o_hi[oi] = hh;
        g_o_lo[oi] = __float2bfloat16(val - __bfloat162float(hh));
    }
}

// ---------------------------------------------------------------------------
__global__ __launch_bounds__(256) void resid_ln_kernel(
    const float* __restrict__ delta,
    const float* __restrict__ gs, const float* __restrict__ gb)
{
    int row = blockIdx.x;
    int d = threadIdx.x;
    int warp = d >> 5, lane = d & 31;
    size_t idx = (size_t)row * D_MODEL + d;
    float t = g_u[idx] + delta[idx];

    __shared__ float sred[8];
    float ws = t;
#pragma unroll
    for (int o = 16; o; o >>= 1) ws += __shfl_xor_sync(0xffffffffu, ws, o);
    if (lane == 0) sred[warp] = ws;
    __syncthreads();
    float tot = 0.f;
#pragma unroll
    for (int i = 0; i < 8; i++) tot += sred[i];
    float mean = tot * (1.0f / D_MODEL);
    __syncthreads();

    float df = t - mean;
    ws = df * df;
#pragma unroll
    for (int o = 16; o; o >>= 1) ws += __shfl_xor_sync(0xffffffffu, ws, o);
    if (lane == 0) sred[warp] = ws;
    __syncthreads();
    tot = 0.f;
#pragma unroll
    for (int i = 0; i < 8; i++) tot += sred[i];
    float var = tot * (1.0f / D_MODEL);

    float y = df * rsqrtf(var + LN_EPS) * gs[d] + gb[d];
    g_u[idx] = y;
    __nv_bfloat16 h = __float2bfloat16(y);
    g_u_hi[idx] = h;
    g_u_lo[idx] = __float2bfloat16(y - __bfloat162float(h));
}

// ---------------------------------------------------------------------------
__global__ __launch_bounds__(96) void head_partial_kernel(const float* __restrict__ Wh)
{
    int d = blockIdx.x;
    int t = threadIdx.x;
    __shared__ float usm[BROWS][TOTAL_S];
    for (int i = t; i < BROWS * TOTAL_S; i += 96) {
        int bcc = i / TOTAL_S, s = i % TOTAL_S;
        usm[bcc][s] = g_u[(size_t)(bcc * TOTAL_S + s) * D_MODEL + d];
    }
    __syncthreads();
    float acc[BROWS];
#pragma unroll
    for (int b = 0; b < BROWS; b++) acc[b] = 0.f;
    for (int s = 0; s < TOTAL_S; s++) {
        float w = Wh[((size_t)d * TOTAL_S + s) * TGT + t];
#pragma unroll
        for (int b = 0; b < BROWS; b++) acc[b] += usm[b][s] * w;
    }
#pragma unroll
    for (int b = 0; b < BROWS; b++)
        g_part[((size_t)d * BROWS + b) * TGT + t] = acc[b];
}

__global__ __launch_bounds__(256) void head_reduce_kernel(
    const float* __restrict__ bh,
    const float* __restrict__ revin_w, const float* __restrict__ revin_b,
    float* __restrict__ out)
{
    int idx = blockIdx.x * blockDim.x + threadIdx.x;
    if (idx >= BROWS * TGT) return;
    int bcc = idx / TGT, t = idx % TGT;
    float acc = 0.f;
    for (int d = 0; d < D_MODEL; d++)
        acc += g_part[((size_t)d * BROWS + bcc) * TGT + t];
    acc += bh[t];
    int c = bcc & 7;
    out[idx] = (acc - revin_b[c]) / (revin_w[c] + 1e-10f) * g_std[bcc] + g_mean[bcc];
}

// ---------------------------------------------------------------------------
extern "C" void kernel_launch(void* const* d_in, const int* in_sizes, int n_in,
                              void* d_out, int out_size)
{
    const float* z       = (const float*)d_in[0];
    const float* revin_w = (const float*)d_in[1];
    const float* revin_b = (const float*)d_in[2];
    const float* Wf      = (const float*)d_in[3];
    const float* bf      = (const float*)d_in[4];
    const float* Wc      = (const float*)d_in[5];
    const float* bcoarse = (const float*)d_in[6];
    const float* Wpos    = (const float*)d_in[7];
    const float* WQ      = (const float*)d_in[8];
    const float* bQ      = (const float*)d_in[9];
    const float* WK      = (const float*)d_in[10];
    const float* bK      = (const float*)d_in[11];
    const float* WV      = (const float*)d_in[12];
    const float* bV      = (const float*)d_in[13];
    const float* WO      = (const float*)d_in[14];
    const float* bO      = (const float*)d_in[15];
    const float* ln1_s   = (const float*)d_in[16];
    const float* ln1_b   = (const float*)d_in[17];
    const float* ln2_s   = (const float*)d_in[18];
    const float* ln2_b   = (const float*)d_in[19];
    const float* F1      = (const float*)d_in[20];
    const float* c1      = (const float*)d_in[21];
    const float* F2      = (const float*)d_in[22];
    const float* c2      = (const float*)d_in[23];
    const float* Wh      = (const float*)d_in[24];
    const float* bh      = (const float*)d_in[25];
    float* out = (float*)d_out;

    float *u, *qkv, *tmp, *bqkv;
    __nv_bfloat16 *uh, *ul, *oh, *ol, *h1h, *h1l, *wth, *wtl;
    cudaGetSymbolAddress((void**)&u,    g_u);
    cudaGetSymbolAddress((void**)&qkv,  g_qkv);
    cudaGetSymbolAddress((void**)&tmp,  g_tmp);
    cudaGetSymbolAddress((void**)&bqkv, g_bqkv);
    cudaGetSymbolAddress((void**)&uh,   g_u_hi);
    cudaGetSymbolAddress((void**)&ul,   g_u_lo);
    cudaGetSymbolAddress((void**)&oh,   g_o_hi);
    cudaGetSymbolAddress((void**)&ol,   g_o_lo);
    cudaGetSymbolAddress((void**)&h1h,  g_h1_hi);
    cudaGetSymbolAddress((void**)&h1l,  g_h1_lo);
    cudaGetSymbolAddress((void**)&wth,  g_wt_hi);
    cudaGetSymbolAddress((void**)&wtl,  g_wt_lo);

    const int SMEM128 = 2 * (2 * 128 * ASTRIDE * 2 + 2 * 128 * ASTRIDE * 2);
    const int SMEM64  = 2 * (2 * 64  * ASTRIDE * 2 + 2 * 128 * ASTRIDE * 2);
    cudaFuncSetAttribute(gemm_tc<0,128>, cudaFuncAttributeMaxDynamicSharedMemorySize, SMEM128);
    cudaFuncSetAttribute(gemm_tc<1,128>, cudaFuncAttributeMaxDynamicSharedMemorySize, SMEM128);
    cudaFuncSetAttribute(gemm_tc<0,64>,  cudaFuncAttributeMaxDynamicSharedMemorySize, SMEM64);
    cudaFuncSetAttribute(attn_kernel,    cudaFuncAttributeMaxDynamicSharedMemorySize, ATTN_SMEM);

    // launch order: 0 wsplit(+bias+stats), 1 embed, 2 QKV gemm, 3 attn (profiled)
    wsplit_all_kernel<<<dim3(256, 8, NLAYERS), 256>>>(WQ, WK, WV, WO, F1, F2,
                                                      bQ, bK, bV, z);
    embed_kernel<<<dim3(TOTAL_S, BROWS), 256>>>(z, revin_w, revin_b,
                                                Wf, bf, Wc, bcoarse, Wpos);

    for (int l = 0; l < NLAYERS; l++) {
        const size_t L = (size_t)l * WSTRIDE;
        gemm_tc<0,128><<<dim3(6, 40), 256, SMEM128>>>(
            uh, ul, wth + L + WOFF_Q, wtl + L + WOFF_Q,
            bqkv + l * 768, qkv, nullptr, nullptr, 768, D_MODEL);
        attn_kernel<<<dim3(5, BROWS * NHEADS), 256, ATTN_SMEM>>>(
            l > 0 ? 1 : 0, l < NLAYERS - 1 ? 1 : 0);
        gemm_tc<0,64><<<dim3(2, 80), 256, SMEM64>>>(
            oh, ol, wth + L + WOFF_O, wtl + L + WOFF_O,
            bO + l * D_MODEL, tmp, nullptr, nullptr, D_MODEL, D_MODEL);
        resid_ln_kernel<<<SEQ, 256>>>(tmp, ln1_s + l * D_MODEL, ln1_b + l * D_MODEL);
        gemm_tc<1,128><<<dim3(8, 40), 256, SMEM128>>>(
            uh, ul, wth + L + WOFF_F1, wtl + L + WOFF_F1,
            c1 + l * DFF, nullptr, h1h, h1l, DFF, D_MODEL);
        gemm_tc<0,64><<<dim3(2, 80), 256, SMEM64>>>(
            h1h, h1l, wth + L + WOFF_F2, wtl + L + WOFF_F2,
            c2 + l * D_MODEL, tmp, nullptr, nullptr, D_MODEL, DFF);
        resid_ln_kernel<<<SEQ, 256>>>(tmp, ln2_s + l * D_MODEL, ln2_b + l * D_MODEL);
    }

    head_partial_kernel<<<D_MODEL, 96>>>(Wh);
    head_reduce_kernel<<<6, 256>>>(bh, revin_w, revin_b, out);
}

// round 12
// speedup vs baseline: 1.2089x; 1.0288x over previous
#include <cuda_runtime.h>
#include <cuda_bf16.h>
#include <math.h>
#include <stdint.h>

#define CTX      1024
#define BROWS    16
#define TOTAL_S  320
#define NF       256
#define D_MODEL  256
#define NHEADS   16
#define DK       16
#define DFF      1024
#define NLAYERS  4
#define TGT      96
#define SEQ      (BROWS * TOTAL_S)   // 5120
#define ATTN_SCALE 0.25f
#define LN_EPS   1e-5f

// ---------------------------------------------------------------------------
// warp MMA + cp.async + f32x2 helpers
// ---------------------------------------------------------------------------
__device__ __forceinline__ uint32_t smem_u32(const void* p) {
    uint32_t a;
    asm("{ .reg .u64 t; cvta.to.shared.u64 t, %1; cvt.u32.u64 %0, t; }"
        : "=r"(a) : "l"(p));
    return a;
}
__device__ __forceinline__ void ldsm_x4(uint32_t& r0, uint32_t& r1,
                                        uint32_t& r2, uint32_t& r3, uint32_t addr) {
    asm volatile("ldmatrix.sync.aligned.m8n8.x4.shared.b16 {%0,%1,%2,%3}, [%4];"
                 : "=r"(r0), "=r"(r1), "=r"(r2), "=r"(r3) : "r"(addr));
}
__device__ __forceinline__ void mma_bf16(float* c, const uint32_t* a, const uint32_t* b) {
    asm volatile(
        "mma.sync.aligned.m16n8k16.row.col.f32.bf16.bf16.f32 "
        "{%0,%1,%2,%3}, {%4,%5,%6,%7}, {%8,%9}, {%0,%1,%2,%3};"
        : "+f"(c[0]), "+f"(c[1]), "+f"(c[2]), "+f"(c[3])
        : "r"(a[0]), "r"(a[1]), "r"(a[2]), "r"(a[3]), "r"(b[0]), "r"(b[1]));
}
#define CP_ASYNC16(dst, src) \
    asm volatile("cp.async.cg.shared.global [%0], [%1], 16;" :: "r"(dst), "l"(src))
#define CP_COMMIT() asm volatile("cp.async.commit_group;" ::: "memory")
#define CP_WAIT0()  asm volatile("cp.async.wait_group 0;" ::: "memory")

// packed f32x2 (Blackwell): 2 fp32 FMA per instruction
#define FFMA2(acc, a, b) \
    asm("fma.rn.f32x2 %0, %1, %2, %0;" : "+l"(acc) : "l"(a), "l"(b))
#define MUL2(out, a, b) \
    asm("mul.rn.f32x2 %0, %1, %2;" : "=l"(out) : "l"(a), "l"(b))
__device__ __forceinline__ unsigned long long pack2(float lo, float hi) {
    unsigned long long r;
    asm("mov.b64 %0, {%1, %2};" : "=l"(r) : "f"(lo), "f"(hi));
    return r;
}
__device__ __forceinline__ void unpack2(unsigned long long v, float& lo, float& hi) {
    asm("mov.b64 {%0, %1}, %2;" : "=f"(lo), "=f"(hi) : "l"(v));
}

// ---------------------------------------------------------------------------
// scratch
// ---------------------------------------------------------------------------
__device__ __align__(256) float g_u[SEQ * D_MODEL];
__device__ __align__(256) float g_qkv[SEQ * 768];
__device__ __align__(256) float g_tmp[SEQ * D_MODEL];
__device__ __align__(256) float g_scores[BROWS * NHEADS * TOTAL_S * TOTAL_S]; // [bh][kk][q]
__device__ float g_mean[BROWS];
__device__ float g_std[BROWS];
__device__ __align__(256) float g_part[D_MODEL * BROWS * TGT];
__device__ __align__(256) float g_bqkv[NLAYERS * 768];

__device__ __align__(256) __nv_bfloat16 g_u_hi[SEQ * D_MODEL];
__device__ __align__(256) __nv_bfloat16 g_u_lo[SEQ * D_MODEL];
__device__ __align__(256) __nv_bfloat16 g_o_hi[SEQ * D_MODEL];
__device__ __align__(256) __nv_bfloat16 g_o_lo[SEQ * D_MODEL];
__device__ __align__(256) __nv_bfloat16 g_h1_hi[SEQ * DFF];
__device__ __align__(256) __nv_bfloat16 g_h1_lo[SEQ * DFF];
#define WOFF_Q   0
#define WOFF_K   65536
#define WOFF_V   131072
#define WOFF_O   196608
#define WOFF_F1  262144
#define WOFF_F2  524288
#define WSTRIDE  786432
__device__ __align__(256) __nv_bfloat16 g_wt_hi[NLAYERS * WSTRIDE];
__device__ __align__(256) __nv_bfloat16 g_wt_lo[NLAYERS * WSTRIDE];

// ---------------------------------------------------------------------------
// merged preprocessing: weight transpose/split, bias pack, RevIN stats
// ---------------------------------------------------------------------------
__global__ __launch_bounds__(256) void wsplit_all_kernel(
    const float* __restrict__ WQ, const float* __restrict__ WK,
    const float* __restrict__ WV, const float* __restrict__ WO,
    const float* __restrict__ F1, const float* __restrict__ F2,
    const float* __restrict__ bQ, const float* __restrict__ bK,
    const float* __restrict__ bV, const float* __restrict__ z)
{
    int kind = blockIdx.y, l = blockIdx.z, tile = blockIdx.x;
    __shared__ float t[32][33];

    if (kind == 6) {
        if (tile >= 3) return;
        int i = tile * 256 + threadIdx.x;
        if (i >= 768) return;
        float v = (i < 256) ? bQ[l * 256 + i]
                : (i < 512) ? bK[l * 256 + i - 256]
                            : bV[l * 256 + i - 512];
        g_bqkv[l * 768 + i] = v;
        return;
    }
    if (kind == 7) {
        if (l != 0 || tile >= BROWS) return;
        int r = tile, tid = threadIdx.x;
        float s = 0.f, s2 = 0.f;
        for (int i = tid; i < CTX; i += 256) {
            float v = z[r * CTX + i];
            s += v; s2 += v * v;
        }
        float* rs = &t[0][0];
        float* rq = rs + 256;
        rs[tid] = s; rq[tid] = s2;
        __syncthreads();
        for (int o = 128; o; o >>= 1) {
            if (tid < o) { rs[tid] += rs[tid + o]; rq[tid] += rq[tid + o]; }
            __syncthreads();
        }
        if (tid == 0) {
            float m = rs[0] / CTX;
            float var = rq[0] / CTX - m * m;
            g_mean[r] = m;
            g_std[r]  = sqrtf(var + LN_EPS);
        }
        return;
    }

    const float* W; int R, C; size_t inl, ooff;
    switch (kind) {
        case 0: W = WQ; R = 256;  C = 256;  inl = 65536;  ooff = WOFF_Q;  break;
        case 1: W = WK; R = 256;  C = 256;  inl = 65536;  ooff = WOFF_K;  break;
        case 2: W = WV; R = 256;  C = 256;  inl = 65536;  ooff = WOFF_V;  break;
        case 3: W = WO; R = 256;  C = 256;  inl = 65536;  ooff = WOFF_O;  break;
        case 4: W = F1; R = 256;  C = 1024; inl = 262144; ooff = WOFF_F1; break;
        default: W = F2; R = 1024; C = 256; inl = 262144; ooff = WOFF_F2; break;
    }
    int ct = C >> 5, rt = R >> 5;
    if (tile >= ct * rt) return;
    int c0 = (tile % ct) << 5, r0 = (tile / ct) << 5;
    const float* Wl = W + (size_t)l * inl;

    int tx = threadIdx.x & 31, ty = threadIdx.x >> 5;
#pragma unroll
    for (int i = 0; i < 32; i += 8)
        t[ty + i][tx] = Wl[(size_t)(r0 + ty + i) * C + c0 + tx];
    __syncthreads();
#pragma unroll
    for (int i = 0; i < 32; i += 8) {
        float x = t[tx][ty + i];
        size_t oi = (size_t)l * WSTRIDE + ooff + (size_t)(c0 + ty + i) * R + (r0 + tx);
        __nv_bfloat16 h = __float2bfloat16(x);
        g_wt_hi[oi] = h;
        g_wt_lo[oi] = __float2bfloat16(x - __bfloat162float(h));
    }
}

// ---------------------------------------------------------------------------
__global__ __launch_bounds__(256) void embed_kernel(
    const float* __restrict__ z,
    const float* __restrict__ revin_w, const float* __restrict__ revin_b,
    const float* __restrict__ Wf, const float* __restrict__ bf,
    const float* __restrict__ Wc, const float* __restrict__ bcoarse,
    const float* __restrict__ Wpos)
{
    int bch = blockIdx.y;
    int s   = blockIdx.x;
    int d   = threadIdx.x;
    int c   = bch & 7;

    __shared__ float patch[32];
    int plen, stride, p;
    const float* W; const float* bias;
    if (s < NF) { plen = 8;  stride = 4;  p = s;      W = Wf; bias = bf; }
    else        { plen = 32; stride = 16; p = s - NF; W = Wc; bias = bcoarse; }

    if (d < plen) {
        int t = p * stride + d;
        if (t > CTX - 1) t = CTX - 1;
        float zv = z[bch * CTX + t];
        patch[d] = (zv - g_mean[bch]) / g_std[bch] * revin_w[c] + revin_b[c];
    }
    __syncthreads();

    float acc = bias[d] + Wpos[s * D_MODEL + d];
    for (int i = 0; i < plen; i++) acc += patch[i] * W[i * D_MODEL + d];
    size_t idx = (size_t)(bch * TOTAL_S + s) * D_MODEL + d;
    g_u[idx] = acc;
    __nv_bfloat16 h = __float2bfloat16(acc);
    g_u_hi[idx] = h;
    g_u_lo[idx] = __float2bfloat16(acc - __bfloat162float(h));
}

// ---------------------------------------------------------------------------
// HMMA bf16x3 GEMM, cp.async 2-stage pipeline, K-chunk 64.
// ---------------------------------------------------------------------------
#define ASTRIDE 72

template<int EPI, int MT>
__global__ __launch_bounds__(256) void gemm_tc(
    const __nv_bfloat16* __restrict__ Ah, const __nv_bfloat16* __restrict__ Al,
    const __nv_bfloat16* __restrict__ Bh, const __nv_bfloat16* __restrict__ Bl,
    const float* __restrict__ bias,
    float* __restrict__ Cf,
    __nv_bfloat16* __restrict__ Chi, __nv_bfloat16* __restrict__ Clo,
    int N, int K)
{
    constexpr int WNs = (MT == 128) ? 2 : 4;
    constexpr int NT  = 16 / WNs;
    constexpr int BUF_A = MT * ASTRIDE * 2;
    constexpr int BUF_B = 128 * ASTRIDE * 2;
    constexpr int STAGE = 2 * BUF_A + 2 * BUF_B;

    extern __shared__ char smem[];
    const uint32_t sbase = smem_u32(smem);

    const int tid = threadIdx.x;
    const int bm = blockIdx.y * MT, bn = blockIdx.x * 128;
    const int warp = tid >> 5, lane = tid & 31;
    const int wm = warp / WNs, wn = warp % WNs;

    const int sr = tid >> 3, sc = (tid & 7) * 8;

    float acc[2][NT][4];
#pragma unroll
    for (int mt = 0; mt < 2; mt++)
#pragma unroll
        for (int nt = 0; nt < NT; nt++)
#pragma unroll
            for (int i = 0; i < 4; i++) acc[mt][nt][i] = 0.f;

    const int gg = lane >> 3, l7 = lane & 7;
    const int a_row = (gg & 1) * 8 + l7;
    const int a_kb  = (gg >> 1) * 16;
    const int b_row = (gg >> 1) * 8 + l7;
    const int b_kb  = (gg & 1) * 16;

    const int nchunk = K >> 6;

#define STAGE_LOAD(kc, s) do { \
        const int _k0 = (kc) << 6; \
        uint32_t _base = sbase + (s) * STAGE; \
        _Pragma("unroll") \
        for (int i = 0; i < MT / 32; i++) { \
            int r = sr + i * 32; \
            uint32_t so = _base + r * 144 + sc * 2; \
            CP_ASYNC16(so, Ah + (size_t)(bm + r) * K + _k0 + sc); \
            CP_ASYNC16(so + BUF_A, Al + (size_t)(bm + r) * K + _k0 + sc); \
        } \
        _Pragma("unroll") \
        for (int i = 0; i < 4; i++) { \
            int r = sr + i * 32; \
            uint32_t so = _base + 2 * BUF_A + r * 144 + sc * 2; \
            CP_ASYNC16(so, Bh + (size_t)(bn + r) * K + _k0 + sc); \
            CP_ASYNC16(so + BUF_B, Bl + (size_t)(bn + r) * K + _k0 + sc); \
        } \
        CP_COMMIT(); \
    } while (0)

    STAGE_LOAD(0, 0);

    for (int kc = 0; kc < nchunk; kc++) {
        CP_WAIT0();
        __syncthreads();
        if (kc + 1 < nchunk) STAGE_LOAD(kc + 1, (kc + 1) & 1);

        const uint32_t base = sbase + (kc & 1) * STAGE;
        const uint32_t uAh = base, uAl = base + BUF_A;
        const uint32_t uBh = base + 2 * BUF_A, uBl = uBh + BUF_B;

#pragma unroll
        for (int ks = 0; ks < 4; ks++) {
            uint32_t ah[2][4], al[2][4], bh[NT][2], bl[NT][2];
#pragma unroll
            for (int mt = 0; mt < 2; mt++) {
                int row = wm * 32 + mt * 16 + a_row;
                uint32_t off = (uint32_t)(row * 144 + ks * 32 + a_kb);
                ldsm_x4(ah[mt][0], ah[mt][1], ah[mt][2], ah[mt][3], uAh + off);
                ldsm_x4(al[mt][0], al[mt][1], al[mt][2], al[mt][3], uAl + off);
            }
#pragma unroll
            for (int j = 0; j < NT / 2; j++) {
                int row = wn * (128 / WNs) + j * 16 + b_row;
                uint32_t off = (uint32_t)(row * 144 + ks * 32 + b_kb);
                uint32_t r0, r1, r2, r3;
                ldsm_x4(r0, r1, r2, r3, uBh + off);
                bh[2 * j][0] = r0; bh[2 * j][1] = r1;
                bh[2 * j + 1][0] = r2; bh[2 * j + 1][1] = r3;
                ldsm_x4(r0, r1, r2, r3, uBl + off);
                bl[2 * j][0] = r0; bl[2 * j][1] = r1;
                bl[2 * j + 1][0] = r2; bl[2 * j + 1][1] = r3;
            }
#pragma unroll
            for (int mt = 0; mt < 2; mt++)
#pragma unroll
                for (int nt = 0; nt < NT; nt++) {
                    mma_bf16(acc[mt][nt], ah[mt], bh[nt]);
                    mma_bf16(acc[mt][nt], ah[mt], bl[nt]);
                    mma_bf16(acc[mt][nt], al[mt], bh[nt]);
                }
        }
        __syncthreads();
    }
#undef STAGE_LOAD

#pragma unroll
    for (int mt = 0; mt < 2; mt++) {
        int row0 = bm + wm * 32 + mt * 16 + (lane >> 2);
#pragma unroll
        for (int nt = 0; nt < NT; nt++) {
            int col = bn + wn * (128 / WNs) + nt * 8 + (lane & 3) * 2;
            float b0 = bias[col], b1 = bias[col + 1];
            float v0 = acc[mt][nt][0] + b0, v1 = acc[mt][nt][1] + b1;
            float v2 = acc[mt][nt][2] + b0, v3 = acc[mt][nt][3] + b1;
            if (EPI == 0) {
                float2 p0 = {v0, v1}, p1 = {v2, v3};
                *(float2*)&Cf[(size_t)row0 * N + col] = p0;
                *(float2*)&Cf[(size_t)(row0 + 8) * N + col] = p1;
            } else {
                v0 = 0.5f * v0 * (1.0f + erff(v0 * 0.7071067811865475f));
                v1 = 0.5f * v1 * (1.0f + erff(v1 * 0.7071067811865475f));
                v2 = 0.5f * v2 * (1.0f + erff(v2 * 0.7071067811865475f));
                v3 = 0.5f * v3 * (1.0f + erff(v3 * 0.7071067811865475f));
                __nv_bfloat162 hh, ll;
                hh.x = __float2bfloat16(v0); hh.y = __float2bfloat16(v1);
                ll.x = __float2bfloat16(v0 - __bfloat162float(hh.x));
                ll.y = __float2bfloat16(v1 - __bfloat162float(hh.y));
                *(__nv_bfloat162*)&Chi[(size_t)row0 * N + col] = hh;
                *(__nv_bfloat162*)&Clo[(size_t)row0 * N + col] = ll;
                hh.x = __float2bfloat16(v2); hh.y = __float2bfloat16(v3);
                ll.x = __float2bfloat16(v2 - __bfloat162float(hh.x));
                ll.y = __float2bfloat16(v3 - __bfloat162float(hh.y));
                *(__nv_bfloat162*)&Chi[(size_t)(row0 + 8) * N + col] = hh;
                *(__nv_bfloat162*)&Clo[(size_t)(row0 + 8) * N + col] = ll;
            }
        }
    }
}

// ---------------------------------------------------------------------------
// fused attention v3: one thread = one q-row; grid = 256 bh, block = 320.
// K/V rows read via broadcast LDS (conflict-free, 16B/instr); online
// block softmax; f32x2 packed FMA; scores stored transposed [bh][kk][q]
// so the residual read/write is warp-coalesced.
// ---------------------------------------------------------------------------
#define ATTN_SMEM (3 * TOTAL_S * DK * 4)   // 61440 B

__global__ __launch_bounds__(320) void attn_kernel(int use_prev, int wr)
{
    extern __shared__ float asm_f[];
    float* Ks = asm_f;                 // [320][16]
    float* Vs = Ks + TOTAL_S * DK;
    float* Qs = Vs + TOTAL_S * DK;

    int bh = blockIdx.x;
    int bc = bh >> 4, h = bh & 15;
    int tid = threadIdx.x;             // q-row

    // stage K/V/Q (float4 chunks)
    for (int i = tid; i < TOTAL_S * 4; i += 320) {
        int s = i >> 2, c = i & 3;
        const float4* src = (const float4*)&g_qkv[(size_t)(bc * TOTAL_S + s) * 768 + (h << 4)];
        *(float4*)&Qs[s * DK + c * 4] = src[c];
        *(float4*)&Ks[s * DK + c * 4] = src[64 + c];
        *(float4*)&Vs[s * DK + c * 4] = src[128 + c];
    }
    __syncthreads();

    // q in packed f32x2 registers
    unsigned long long q2[8];
    {
        const ulonglong2* qp = (const ulonglong2*)&Qs[tid * DK];
#pragma unroll
        for (int c = 0; c < 4; c++) {
            ulonglong2 v = qp[c];
            q2[2 * c] = v.x; q2[2 * c + 1] = v.y;
        }
    }

    float m = -1e30f, sden = 0.f;
    unsigned long long o2[8];
#pragma unroll
    for (int c = 0; c < 8; c++) o2[c] = 0ULL;

    float* srow = &g_scores[(size_t)bh * TOTAL_S * TOTAL_S];  // [kk][q]

#pragma unroll 1
    for (int blk = 0; blk < 40; blk++) {
        float sc[8];
#pragma unroll
        for (int t = 0; t < 8; t++) {
            int kk = blk * 8 + t;
            const ulonglong2* kp = (const ulonglong2*)&Ks[kk * DK];
            unsigned long long acc2 = 0ULL;
#pragma unroll
            for (int c = 0; c < 4; c++) {
                ulonglong2 kv = kp[c];                  // broadcast LDS.128
                FFMA2(acc2, q2[2 * c], kv.x);
                FFMA2(acc2, q2[2 * c + 1], kv.y);
            }
            float lo, hi; unpack2(acc2, lo, hi);
            float s = (lo + hi) * ATTN_SCALE;
            if (use_prev) s += srow[(size_t)kk * TOTAL_S + tid];
            sc[t] = s;
            if (wr) srow[(size_t)kk * TOTAL_S + tid] = s;
        }
        float bm = sc[0];
#pragma unroll
        for (int t = 1; t < 8; t++) bm = fmaxf(bm, sc[t]);
        float mn = fmaxf(m, bm);
        float corr = __expf(m - mn);
        sden *= corr;
        unsigned long long c2 = pack2(corr, corr);
#pragma unroll
        for (int c = 0; c < 8; c++) MUL2(o2[c], o2[c], c2);
#pragma unroll
        for (int t = 0; t < 8; t++) {
            int kk = blk * 8 + t;
            float p = __expf(sc[t] - mn);
            sden += p;
            unsigned long long p2 = pack2(p, p);
            const ulonglong2* vp = (const ulonglong2*)&Vs[kk * DK];
#pragma unroll
            for (int c = 0; c < 4; c++) {
                ulonglong2 vv = vp[c];                  // broadcast LDS.128
                FFMA2(o2[2 * c], p2, vv.x);
                FFMA2(o2[2 * c + 1], p2, vv.y);
            }
        }
        m = mn;
    }

    float inv = 1.f / sden;
    size_t ob = (size_t)(bc * TOTAL_S + tid) * D_MODEL + (h << 4);
#pragma unroll
    for (int c = 0; c < 8; c++) {
        float v0, v1; unpack2(o2[c], v0, v1);
        v0 *= inv; v1 *= inv;
        __nv_bfloat162 hh, ll;
        hh.x = __float2bfloat16(v0); hh.y = __float2bfloat16(v1);
        ll.x = __float2bfloat16(v0 - __bfloat162float(hh.x));
        ll.y = __float2bfloat16(v1 - __bfloat162float(hh.y));
        *(__nv_bfloat162*)&g_o_hi[ob + c * 2] = hh;
        *(__nv_bfloat162*)&g_o_lo[ob + c * 2] = ll;
    }
}

// ---------------------------------------------------------------------------
__global__ __launch_bounds__(256) void resid_ln_kernel(
    const float* __restrict__ delta,
    const float* __restrict__ gs, const float* __restrict__ gb)
{
    int row = blockIdx.x;
    int d = threadIdx.x;
    int warp = d >> 5, lane = d & 31;
    size_t idx = (size_t)row * D_MODEL + d;
    float t = g_u[idx] + delta[idx];

    __shared__ float sred[8];
    float ws = t;
#pragma unroll
    for (int o = 16; o; o >>= 1) ws += __shfl_xor_sync(0xffffffffu, ws, o);
    if (lane == 0) sred[warp] = ws;
    __syncthreads();
    float tot = 0.f;
#pragma unroll
    for (int i = 0; i < 8; i++) tot += sred[i];
    float mean = tot * (1.0f / D_MODEL);
    __syncthreads();

    float df = t - mean;
    ws = df * df;
#pragma unroll
    for (int o = 16; o; o >>= 1) ws += __shfl_xor_sync(0xffffffffu, ws, o);
    if (lane == 0) sred[warp] = ws;
    __syncthreads();
    tot = 0.f;
#pragma unroll
    for (int i = 0; i < 8; i++) tot += sred[i];
    float var = tot * (1.0f / D_MODEL);

    float y = df * rsqrtf(var + LN_EPS) * gs[d] + gb[d];
    g_u[idx] = y;
    __nv_bfloat16 h = __float2bfloat16(y);
    g_u_hi[idx] = h;
    g_u_lo[idx] = __float2bfloat16(y - __bfloat162float(h));
}

// ---------------------------------------------------------------------------
__global__ __launch_bounds__(96) void head_partial_kernel(const float* __restrict__ Wh)
{
    int d = blockIdx.x;
    int t = threadIdx.x;
    __shared__ float usm[BROWS][TOTAL_S];
    for (int i = t; i < BROWS * TOTAL_S; i += 96) {
        int bcc = i / TOTAL_S, s = i % TOTAL_S;
        usm[bcc][s] = g_u[(size_t)(bcc * TOTAL_S + s) * D_MODEL + d];
    }
    __syncthreads();
    float acc[BROWS];
#pragma unroll
    for (int b = 0; b < BROWS; b++) acc[b] = 0.f;
    for (int s = 0; s < TOTAL_S; s++) {
        float w = Wh[((size_t)d * TOTAL_S + s) * TGT + t];
#pragma unroll
        for (int b = 0; b < BROWS; b++) acc[b] += usm[b][s] * w;
    }
#pragma unroll
    for (int b = 0; b < BROWS; b++)
        g_part[((size_t)d * BROWS + b) * TGT + t] = acc[b];
}

__global__ __launch_bounds__(256) void head_reduce_kernel(
    const float* __restrict__ bh,
    const float* __restrict__ revin_w, const float* __restrict__ revin_b,
    float* __restrict__ out)
{
    int idx = blockIdx.x * blockDim.x + threadIdx.x;
    if (idx >= BROWS * TGT) return;
    int bcc = idx / TGT, t = idx % TGT;
    float acc = 0.f;
    for (int d = 0; d < D_MODEL; d++)
        acc += g_part[((size_t)d * BROWS + bcc) * TGT + t];
    acc += bh[t];
    int c = bcc & 7;
    out[idx] = (acc - revin_b[c]) / (revin_w[c] + 1e-10f) * g_std[bcc] + g_mean[bcc];
}

// ---------------------------------------------------------------------------
extern "C" void kernel_launch(void* const* d_in, const int* in_sizes, int n_in,
                              void* d_out, int out_size)
{
    const float* z       = (const float*)d_in[0];
    const float* revin_w = (const float*)d_in[1];
    const float* revin_b = (const float*)d_in[2];
    const float* Wf      = (const float*)d_in[3];
    const float* bf      = (const float*)d_in[4];
    const float* Wc      = (const float*)d_in[5];
    const float* bcoarse = (const float*)d_in[6];
    const float* Wpos    = (const float*)d_in[7];
    const float* WQ      = (const float*)d_in[8];
    const float* bQ      = (const float*)d_in[9];
    const float* WK      = (const float*)d_in[10];
    const float* bK      = (const float*)d_in[11];
    const float* WV      = (const float*)d_in[12];
    const float* bV      = (const float*)d_in[13];
    const float* WO      = (const float*)d_in[14];
    const float* bO      = (const float*)d_in[15];
    const float* ln1_s   = (const float*)d_in[16];
    const float* ln1_b   = (const float*)d_in[17];
    const float* ln2_s   = (const float*)d_in[18];
    const float* ln2_b   = (const float*)d_in[19];
    const float* F1      = (const float*)d_in[20];
    const float* c1      = (const float*)d_in[21];
    const float* F2      = (const float*)d_in[22];
    const float* c2      = (const float*)d_in[23];
    const float* Wh      = (const float*)d_in[24];
    const float* bh      = (const float*)d_in[25];
    float* out = (float*)d_out;

    float *u, *qkv, *tmp, *bqkv;
    __nv_bfloat16 *uh, *ul, *oh, *ol, *h1h, *h1l, *wth, *wtl;
    cudaGetSymbolAddress((void**)&u,    g_u);
    cudaGetSymbolAddress((void**)&qkv,  g_qkv);
    cudaGetSymbolAddress((void**)&tmp,  g_tmp);
    cudaGetSymbolAddress((void**)&bqkv, g_bqkv);
    cudaGetSymbolAddress((void**)&uh,   g_u_hi);
    cudaGetSymbolAddress((void**)&ul,   g_u_lo);
    cudaGetSymbolAddress((void**)&oh,   g_o_hi);
    cudaGetSymbolAddress((void**)&ol,   g_o_lo);
    cudaGetSymbolAddress((void**)&h1h,  g_h1_hi);
    cudaGetSymbolAddress((void**)&h1l,  g_h1_lo);
    cudaGetSymbolAddress((void**)&wth,  g_wt_hi);
    cudaGetSymbolAddress((void**)&wtl,  g_wt_lo);

    const int SMEM128 = 2 * (2 * 128 * ASTRIDE * 2 + 2 * 128 * ASTRIDE * 2);
    const int SMEM64  = 2 * (2 * 64  * ASTRIDE * 2 + 2 * 128 * ASTRIDE * 2);
    cudaFuncSetAttribute(gemm_tc<0,128>, cudaFuncAttributeMaxDynamicSharedMemorySize, SMEM128);
    cudaFuncSetAttribute(gemm_tc<1,128>, cudaFuncAttributeMaxDynamicSharedMemorySize, SMEM128);
    cudaFuncSetAttribute(gemm_tc<0,64>,  cudaFuncAttributeMaxDynamicSharedMemorySize, SMEM64);
    cudaFuncSetAttribute(attn_kernel,    cudaFuncAttributeMaxDynamicSharedMemorySize, ATTN_SMEM);

    // launch order: 0 wsplit(+bias+stats), 1 embed, 2 QKV gemm, 3 attn (profiled)
    wsplit_all_kernel<<<dim3(256, 8, NLAYERS), 256>>>(WQ, WK, WV, WO, F1, F2,
                                                      bQ, bK, bV, z);
    embed_kernel<<<dim3(TOTAL_S, BROWS), 256>>>(z, revin_w, revin_b,
                                                Wf, bf, Wc, bcoarse, Wpos);

    for (int l = 0; l < NLAYERS; l++) {
        const size_t L = (size_t)l * WSTRIDE;
        gemm_tc<0,128><<<dim3(6, 40), 256, SMEM128>>>(
            uh, ul, wth + L + WOFF_Q, wtl + L + WOFF_Q,
            bqkv + l * 768, qkv, nullptr, nullptr, 768, D_MODEL);
        attn_kernel<<<BROWS * NHEADS, 320, ATTN_SMEM>>>(
            l > 0 ? 1 : 0, l < NLAYERS - 1 ? 1 : 0);
        gemm_tc<0,64><<<dim3(2, 80), 256, SMEM64>>>(
            oh, ol, wth + L + WOFF_O, wtl + L + WOFF_O,
            bO + l * D_MODEL, tmp, nullptr, nullptr, D_MODEL, D_MODEL);
        resid_ln_kernel<<<SEQ, 256>>>(tmp, ln1_s + l * D_MODEL, ln1_b + l * D_MODEL);
        gemm_tc<1,128><<<dim3(8, 40), 256, SMEM128>>>(
            uh, ul, wth + L + WOFF_F1, wtl + L + WOFF_F1,
            c1 + l * DFF, nullptr, h1h, h1l, DFF, D_MODEL);
        gemm_tc<0,64><<<dim3(2, 80), 256, SMEM64>>>(
            h1h, h1l, wth + L + WOFF_F2, wtl + L + WOFF_F2,
            c2 + l * D_MODEL, tmp, nullptr, nullptr, D_MODEL, DFF);
        resid_ln_kernel<<<SEQ, 256>>>(tmp, ln2_s + l * D_MODEL, ln2_b + l * D_MODEL);
    }

    head_partial_kernel<<<D_MODEL, 96>>>(Wh);
    head_reduce_kernel<<<6, 256>>>(bh, revin_w, revin_b, out);
}

// round 13
// speedup vs baseline: 1.2279x; 1.0157x over previous
#include <cuda_runtime.h>
#include <cuda_bf16.h>
#include <math.h>
#include <stdint.h>

#define CTX      1024
#define BROWS    16
#define TOTAL_S  320
#define NF       256
#define D_MODEL  256
#define NHEADS   16
#define DK       16
#define DFF      1024
#define NLAYERS  4
#define TGT      96
#define SEQ      (BROWS * TOTAL_S)   // 5120
#define ATTN_SCALE 0.25f
#define LN_EPS   1e-5f

// ---------------------------------------------------------------------------
// warp MMA + cp.async + f32x2 helpers
// ---------------------------------------------------------------------------
__device__ __forceinline__ uint32_t smem_u32(const void* p) {
    uint32_t a;
    asm("{ .reg .u64 t; cvta.to.shared.u64 t, %1; cvt.u32.u64 %0, t; }"
        : "=r"(a) : "l"(p));
    return a;
}
__device__ __forceinline__ void ldsm_x4(uint32_t& r0, uint32_t& r1,
                                        uint32_t& r2, uint32_t& r3, uint32_t addr) {
    asm volatile("ldmatrix.sync.aligned.m8n8.x4.shared.b16 {%0,%1,%2,%3}, [%4];"
                 : "=r"(r0), "=r"(r1), "=r"(r2), "=r"(r3) : "r"(addr));
}
__device__ __forceinline__ void mma_bf16(float* c, const uint32_t* a, const uint32_t* b) {
    asm volatile(
        "mma.sync.aligned.m16n8k16.row.col.f32.bf16.bf16.f32 "
        "{%0,%1,%2,%3}, {%4,%5,%6,%7}, {%8,%9}, {%0,%1,%2,%3};"
        : "+f"(c[0]), "+f"(c[1]), "+f"(c[2]), "+f"(c[3])
        : "r"(a[0]), "r"(a[1]), "r"(a[2]), "r"(a[3]), "r"(b[0]), "r"(b[1]));
}
#define CP_ASYNC16(dst, src) \
    asm volatile("cp.async.cg.shared.global [%0], [%1], 16;" :: "r"(dst), "l"(src))
#define CP_COMMIT() asm volatile("cp.async.commit_group;" ::: "memory")
#define CP_WAIT0()  asm volatile("cp.async.wait_group 0;" ::: "memory")

// packed f32x2 (Blackwell): 2 fp32 FMA per instruction
#define FFMA2(acc, a, b) \
    asm("fma.rn.f32x2 %0, %1, %2, %0;" : "+l"(acc) : "l"(a), "l"(b))
#define MUL2(out, a, b) \
    asm("mul.rn.f32x2 %0, %1, %2;" : "=l"(out) : "l"(a), "l"(b))
__device__ __forceinline__ unsigned long long pack2(float lo, float hi) {
    unsigned long long r;
    asm("mov.b64 %0, {%1, %2};" : "=l"(r) : "f"(lo), "f"(hi));
    return r;
}
__device__ __forceinline__ void unpack2(unsigned long long v, float& lo, float& hi) {
    asm("mov.b64 {%0, %1}, %2;" : "=f"(lo), "=f"(hi) : "l"(v));
}

// ---------------------------------------------------------------------------
// scratch
// ---------------------------------------------------------------------------
__device__ __align__(256) float g_u[SEQ * D_MODEL];
__device__ __align__(256) float g_qkv[SEQ * 768];
__device__ __align__(256) float g_tmp[SEQ * D_MODEL];
__device__ __align__(256) float g_scores[BROWS * NHEADS * TOTAL_S * TOTAL_S]; // [bh][kk][q]
__device__ float g_mean[BROWS];
__device__ float g_std[BROWS];
__device__ __align__(256) float g_part[D_MODEL * BROWS * TGT];
__device__ __align__(256) float g_bqkv[NLAYERS * 768];

__device__ __align__(256) __nv_bfloat16 g_u_hi[SEQ * D_MODEL];
__device__ __align__(256) __nv_bfloat16 g_u_lo[SEQ * D_MODEL];
__device__ __align__(256) __nv_bfloat16 g_o_hi[SEQ * D_MODEL];
__device__ __align__(256) __nv_bfloat16 g_o_lo[SEQ * D_MODEL];
__device__ __align__(256) __nv_bfloat16 g_h1_hi[SEQ * DFF];
__device__ __align__(256) __nv_bfloat16 g_h1_lo[SEQ * DFF];
#define WOFF_Q   0
#define WOFF_K   65536
#define WOFF_V   131072
#define WOFF_O   196608
#define WOFF_F1  262144
#define WOFF_F2  524288
#define WSTRIDE  786432
__device__ __align__(256) __nv_bfloat16 g_wt_hi[NLAYERS * WSTRIDE];
__device__ __align__(256) __nv_bfloat16 g_wt_lo[NLAYERS * WSTRIDE];

// ---------------------------------------------------------------------------
// merged preprocessing: weight transpose/split, bias pack, RevIN stats
// ---------------------------------------------------------------------------
__global__ __launch_bounds__(256) void wsplit_all_kernel(
    const float* __restrict__ WQ, const float* __restrict__ WK,
    const float* __restrict__ WV, const float* __restrict__ WO,
    const float* __restrict__ F1, const float* __restrict__ F2,
    const float* __restrict__ bQ, const float* __restrict__ bK,
    const float* __restrict__ bV, const float* __restrict__ z)
{
    int kind = blockIdx.y, l = blockIdx.z, tile = blockIdx.x;
    __shared__ float t[32][33];

    if (kind == 6) {
        if (tile >= 3) return;
        int i = tile * 256 + threadIdx.x;
        if (i >= 768) return;
        float v = (i < 256) ? bQ[l * 256 + i]
                : (i < 512) ? bK[l * 256 + i - 256]
                            : bV[l * 256 + i - 512];
        g_bqkv[l * 768 + i] = v;
        return;
    }
    if (kind == 7) {
        if (l != 0 || tile >= BROWS) return;
        int r = tile, tid = threadIdx.x;
        float s = 0.f, s2 = 0.f;
        for (int i = tid; i < CTX; i += 256) {
            float v = z[r * CTX + i];
            s += v; s2 += v * v;
        }
        float* rs = &t[0][0];
        float* rq = rs + 256;
        rs[tid] = s; rq[tid] = s2;
        __syncthreads();
        for (int o = 128; o; o >>= 1) {
            if (tid < o) { rs[tid] += rs[tid + o]; rq[tid] += rq[tid + o]; }
            __syncthreads();
        }
        if (tid == 0) {
            float m = rs[0] / CTX;
            float var = rq[0] / CTX - m * m;
            g_mean[r] = m;
            g_std[r]  = sqrtf(var + LN_EPS);
        }
        return;
    }

    const float* W; int R, C; size_t inl, ooff;
    switch (kind) {
        case 0: W = WQ; R = 256;  C = 256;  inl = 65536;  ooff = WOFF_Q;  break;
        case 1: W = WK; R = 256;  C = 256;  inl = 65536;  ooff = WOFF_K;  break;
        case 2: W = WV; R = 256;  C = 256;  inl = 65536;  ooff = WOFF_V;  break;
        case 3: W = WO; R = 256;  C = 256;  inl = 65536;  ooff = WOFF_O;  break;
        case 4: W = F1; R = 256;  C = 1024; inl = 262144; ooff = WOFF_F1; break;
        default: W = F2; R = 1024; C = 256; inl = 262144; ooff = WOFF_F2; break;
    }
    int ct = C >> 5, rt = R >> 5;
    if (tile >= ct * rt) return;
    int c0 = (tile % ct) << 5, r0 = (tile / ct) << 5;
    const float* Wl = W + (size_t)l * inl;

    int tx = threadIdx.x & 31, ty = threadIdx.x >> 5;
#pragma unroll
    for (int i = 0; i < 32; i += 8)
        t[ty + i][tx] = Wl[(size_t)(r0 + ty + i) * C + c0 + tx];
    __syncthreads();
#pragma unroll
    for (int i = 0; i < 32; i += 8) {
        float x = t[tx][ty + i];
        size_t oi = (size_t)l * WSTRIDE + ooff + (size_t)(c0 + ty + i) * R + (r0 + tx);
        __nv_bfloat16 h = __float2bfloat16(x);
        g_wt_hi[oi] = h;
        g_wt_lo[oi] = __float2bfloat16(x - __bfloat162float(h));
    }
}

// ---------------------------------------------------------------------------
__global__ __launch_bounds__(256) void embed_kernel(
    const float* __restrict__ z,
    const float* __restrict__ revin_w, const float* __restrict__ revin_b,
    const float* __restrict__ Wf, const float* __restrict__ bf,
    const float* __restrict__ Wc, const float* __restrict__ bcoarse,
    const float* __restrict__ Wpos)
{
    int bch = blockIdx.y;
    int s   = blockIdx.x;
    int d   = threadIdx.x;
    int c   = bch & 7;

    __shared__ float patch[32];
    int plen, stride, p;
    const float* W; const float* bias;
    if (s < NF) { plen = 8;  stride = 4;  p = s;      W = Wf; bias = bf; }
    else        { plen = 32; stride = 16; p = s - NF; W = Wc; bias = bcoarse; }

    if (d < plen) {
        int t = p * stride + d;
        if (t > CTX - 1) t = CTX - 1;
        float zv = z[bch * CTX + t];
        patch[d] = (zv - g_mean[bch]) / g_std[bch] * revin_w[c] + revin_b[c];
    }
    __syncthreads();

    float acc = bias[d] + Wpos[s * D_MODEL + d];
    for (int i = 0; i < plen; i++) acc += patch[i] * W[i * D_MODEL + d];
    size_t idx = (size_t)(bch * TOTAL_S + s) * D_MODEL + d;
    g_u[idx] = acc;
    __nv_bfloat16 h = __float2bfloat16(acc);
    g_u_hi[idx] = h;
    g_u_lo[idx] = __float2bfloat16(acc - __bfloat162float(h));
}

// ---------------------------------------------------------------------------
// HMMA bf16x3 GEMM, cp.async 2-stage pipeline, K-chunk 64.
// MT=64 everywhere now: SMEM 110.5KB -> 2 CTAs/SM.
// ---------------------------------------------------------------------------
#define ASTRIDE 72

template<int EPI, int MT>
__global__ __launch_bounds__(256) void gemm_tc(
    const __nv_bfloat16* __restrict__ Ah, const __nv_bfloat16* __restrict__ Al,
    const __nv_bfloat16* __restrict__ Bh, const __nv_bfloat16* __restrict__ Bl,
    const float* __restrict__ bias,
    float* __restrict__ Cf,
    __nv_bfloat16* __restrict__ Chi, __nv_bfloat16* __restrict__ Clo,
    int N, int K)
{
    constexpr int WNs = (MT == 128) ? 2 : 4;
    constexpr int NT  = 16 / WNs;
    constexpr int BUF_A = MT * ASTRIDE * 2;
    constexpr int BUF_B = 128 * ASTRIDE * 2;
    constexpr int STAGE = 2 * BUF_A + 2 * BUF_B;

    extern __shared__ char smem[];
    const uint32_t sbase = smem_u32(smem);

    const int tid = threadIdx.x;
    const int bm = blockIdx.y * MT, bn = blockIdx.x * 128;
    const int warp = tid >> 5, lane = tid & 31;
    const int wm = warp / WNs, wn = warp % WNs;

    const int sr = tid >> 3, sc = (tid & 7) * 8;

    float acc[2][NT][4];
#pragma unroll
    for (int mt = 0; mt < 2; mt++)
#pragma unroll
        for (int nt = 0; nt < NT; nt++)
#pragma unroll
            for (int i = 0; i < 4; i++) acc[mt][nt][i] = 0.f;

    const int gg = lane >> 3, l7 = lane & 7;
    const int a_row = (gg & 1) * 8 + l7;
    const int a_kb  = (gg >> 1) * 16;
    const int b_row = (gg >> 1) * 8 + l7;
    const int b_kb  = (gg & 1) * 16;

    const int nchunk = K >> 6;

#define STAGE_LOAD(kc, s) do { \
        const int _k0 = (kc) << 6; \
        uint32_t _base = sbase + (s) * STAGE; \
        _Pragma("unroll") \
        for (int i = 0; i < MT / 32; i++) { \
            int r = sr + i * 32; \
            uint32_t so = _base + r * 144 + sc * 2; \
            CP_ASYNC16(so, Ah + (size_t)(bm + r) * K + _k0 + sc); \
            CP_ASYNC16(so + BUF_A, Al + (size_t)(bm + r) * K + _k0 + sc); \
        } \
        _Pragma("unroll") \
        for (int i = 0; i < 4; i++) { \
            int r = sr + i * 32; \
            uint32_t so = _base + 2 * BUF_A + r * 144 + sc * 2; \
            CP_ASYNC16(so, Bh + (size_t)(bn + r) * K + _k0 + sc); \
            CP_ASYNC16(so + BUF_B, Bl + (size_t)(bn + r) * K + _k0 + sc); \
        } \
        CP_COMMIT(); \
    } while (0)

    STAGE_LOAD(0, 0);

    for (int kc = 0; kc < nchunk; kc++) {
        CP_WAIT0();
        __syncthreads();
        if (kc + 1 < nchunk) STAGE_LOAD(kc + 1, (kc + 1) & 1);

        const uint32_t base = sbase + (kc & 1) * STAGE;
        const uint32_t uAh = base, uAl = base + BUF_A;
        const uint32_t uBh = base + 2 * BUF_A, uBl = uBh + BUF_B;

#pragma unroll
        for (int ks = 0; ks < 4; ks++) {
            uint32_t ah[2][4], al[2][4], bh[NT][2], bl[NT][2];
#pragma unroll
            for (int mt = 0; mt < 2; mt++) {
                int row = wm * 32 + mt * 16 + a_row;
                uint32_t off = (uint32_t)(row * 144 + ks * 32 + a_kb);
                ldsm_x4(ah[mt][0], ah[mt][1], ah[mt][2], ah[mt][3], uAh + off);
                ldsm_x4(al[mt][0], al[mt][1], al[mt][2], al[mt][3], uAl + off);
            }
#pragma unroll
            for (int j = 0; j < NT / 2; j++) {
                int row = wn * (128 / WNs) + j * 16 + b_row;
                uint32_t off = (uint32_t)(row * 144 + ks * 32 + b_kb);
                uint32_t r0, r1, r2, r3;
                ldsm_x4(r0, r1, r2, r3, uBh + off);
                bh[2 * j][0] = r0; bh[2 * j][1] = r1;
                bh[2 * j + 1][0] = r2; bh[2 * j + 1][1] = r3;
                ldsm_x4(r0, r1, r2, r3, uBl + off);
                bl[2 * j][0] = r0; bl[2 * j][1] = r1;
                bl[2 * j + 1][0] = r2; bl[2 * j + 1][1] = r3;
            }
#pragma unroll
            for (int mt = 0; mt < 2; mt++)
#pragma unroll
                for (int nt = 0; nt < NT; nt++) {
                    mma_bf16(acc[mt][nt], ah[mt], bh[nt]);
                    mma_bf16(acc[mt][nt], ah[mt], bl[nt]);
                    mma_bf16(acc[mt][nt], al[mt], bh[nt]);
                }
        }
        __syncthreads();
    }
#undef STAGE_LOAD

#pragma unroll
    for (int mt = 0; mt < 2; mt++) {
        int row0 = bm + wm * 32 + mt * 16 + (lane >> 2);
#pragma unroll
        for (int nt = 0; nt < NT; nt++) {
            int col = bn + wn * (128 / WNs) + nt * 8 + (lane & 3) * 2;
            float b0 = bias[col], b1 = bias[col + 1];
            float v0 = acc[mt][nt][0] + b0, v1 = acc[mt][nt][1] + b1;
            float v2 = acc[mt][nt][2] + b0, v3 = acc[mt][nt][3] + b1;
            if (EPI == 0) {
                float2 p0 = {v0, v1}, p1 = {v2, v3};
                *(float2*)&Cf[(size_t)row0 * N + col] = p0;
                *(float2*)&Cf[(size_t)(row0 + 8) * N + col] = p1;
            } else {
                v0 = 0.5f * v0 * (1.0f + erff(v0 * 0.7071067811865475f));
                v1 = 0.5f * v1 * (1.0f + erff(v1 * 0.7071067811865475f));
                v2 = 0.5f * v2 * (1.0f + erff(v2 * 0.7071067811865475f));
                v3 = 0.5f * v3 * (1.0f + erff(v3 * 0.7071067811865475f));
                __nv_bfloat162 hh, ll;
                hh.x = __float2bfloat16(v0); hh.y = __float2bfloat16(v1);
                ll.x = __float2bfloat16(v0 - __bfloat162float(hh.x));
                ll.y = __float2bfloat16(v1 - __bfloat162float(hh.y));
                *(__nv_bfloat162*)&Chi[(size_t)row0 * N + col] = hh;
                *(__nv_bfloat162*)&Clo[(size_t)row0 * N + col] = ll;
                hh.x = __float2bfloat16(v2); hh.y = __float2bfloat16(v3);
                ll.x = __float2bfloat16(v2 - __bfloat162float(hh.x));
                ll.y = __float2bfloat16(v3 - __bfloat162float(hh.y));
                *(__nv_bfloat162*)&Chi[(size_t)(row0 + 8) * N + col] = hh;
                *(__nv_bfloat162*)&Clo[(size_t)(row0 + 8) * N + col] = ll;
            }
        }
    }
}

// ---------------------------------------------------------------------------
// fused attention v3 (R12): one thread = one q-row; broadcast LDS; online
// softmax; f32x2 FMA; scores transposed [bh][kk][q].
// ---------------------------------------------------------------------------
#define ATTN_SMEM (3 * TOTAL_S * DK * 4)   // 61440 B

__global__ __launch_bounds__(320) void attn_kernel(int use_prev, int wr)
{
    extern __shared__ float asm_f[];
    float* Ks = asm_f;
    float* Vs = Ks + TOTAL_S * DK;
    float* Qs = Vs + TOTAL_S * DK;

    int bh = blockIdx.x;
    int bc = bh >> 4, h = bh & 15;
    int tid = threadIdx.x;

    for (int i = tid; i < TOTAL_S * 4; i += 320) {
        int s = i >> 2, c = i & 3;
        const float4* src = (const float4*)&g_qkv[(size_t)(bc * TOTAL_S + s) * 768 + (h << 4)];
        *(float4*)&Qs[s * DK + c * 4] = src[c];
        *(float4*)&Ks[s * DK + c * 4] = src[64 + c];
        *(float4*)&Vs[s * DK + c * 4] = src[128 + c];
    }
    __syncthreads();

    unsigned long long q2[8];
    {
        const ulonglong2* qp = (const ulonglong2*)&Qs[tid * DK];
#pragma unroll
        for (int c = 0; c < 4; c++) {
            ulonglong2 v = qp[c];
            q2[2 * c] = v.x; q2[2 * c + 1] = v.y;
        }
    }

    float m = -1e30f, sden = 0.f;
    unsigned long long o2[8];
#pragma unroll
    for (int c = 0; c < 8; c++) o2[c] = 0ULL;

    float* srow = &g_scores[(size_t)bh * TOTAL_S * TOTAL_S];

#pragma unroll 1
    for (int blk = 0; blk < 40; blk++) {
        float sc[8];
#pragma unroll
        for (int t = 0; t < 8; t++) {
            int kk = blk * 8 + t;
            const ulonglong2* kp = (const ulonglong2*)&Ks[kk * DK];
            unsigned long long acc2 = 0ULL;
#pragma unroll
            for (int c = 0; c < 4; c++) {
                ulonglong2 kv = kp[c];
                FFMA2(acc2, q2[2 * c], kv.x);
                FFMA2(acc2, q2[2 * c + 1], kv.y);
            }
            float lo, hi; unpack2(acc2, lo, hi);
            float s = (lo + hi) * ATTN_SCALE;
            if (use_prev) s += srow[(size_t)kk * TOTAL_S + tid];
            sc[t] = s;
            if (wr) srow[(size_t)kk * TOTAL_S + tid] = s;
        }
        float bm = sc[0];
#pragma unroll
        for (int t = 1; t < 8; t++) bm = fmaxf(bm, sc[t]);
        float mn = fmaxf(m, bm);
        float corr = __expf(m - mn);
        sden *= corr;
        unsigned long long c2 = pack2(corr, corr);
#pragma unroll
        for (int c = 0; c < 8; c++) MUL2(o2[c], o2[c], c2);
#pragma unroll
        for (int t = 0; t < 8; t++) {
            int kk = blk * 8 + t;
            float p = __expf(sc[t] - mn);
            sden += p;
            unsigned long long p2 = pack2(p, p);
            const ulonglong2* vp = (const ulonglong2*)&Vs[kk * DK];
#pragma unroll
            for (int c = 0; c < 4; c++) {
                ulonglong2 vv = vp[c];
                FFMA2(o2[2 * c], p2, vv.x);
                FFMA2(o2[2 * c + 1], p2, vv.y);
            }
        }
        m = mn;
    }

    float inv = 1.f / sden;
    size_t ob = (size_t)(bc * TOTAL_S + tid) * D_MODEL + (h << 4);
#pragma unroll
    for (int c = 0; c < 8; c++) {
        float v0, v1; unpack2(o2[c], v0, v1);
        v0 *= inv; v1 *= inv;
        __nv_bfloat162 hh, ll;
        hh.x = __float2bfloat16(v0); hh.y = __float2bfloat16(v1);
        ll.x = __float2bfloat16(v0 - __bfloat162float(hh.x));
        ll.y = __float2bfloat16(v1 - __bfloat162float(hh.y));
        *(__nv_bfloat162*)&g_o_hi[ob + c * 2] = hh;
        *(__nv_bfloat162*)&g_o_lo[ob + c * 2] = ll;
    }
}

// ---------------------------------------------------------------------------
__global__ __launch_bounds__(256) void resid_ln_kernel(
    const float* __restrict__ delta,
    const float* __restrict__ gs, const float* __restrict__ gb)
{
    int row = blockIdx.x;
    int d = threadIdx.x;
    int warp = d >> 5, lane = d & 31;
    size_t idx = (size_t)row * D_MODEL + d;
    float t = g_u[idx] + delta[idx];

    __shared__ float sred[8];
    float ws = t;
#pragma unroll
    for (int o = 16; o; o >>= 1) ws += __shfl_xor_sync(0xffffffffu, ws, o);
    if (lane == 0) sred[warp] = ws;
    __syncthreads();
    float tot = 0.f;
#pragma unroll
    for (int i = 0; i < 8; i++) tot += sred[i];
    float mean = tot * (1.0f / D_MODEL);
    __syncthreads();

    float df = t - mean;
    ws = df * df;
#pragma unroll
    for (int o = 16; o; o >>= 1) ws += __shfl_xor_sync(0xffffffffu, ws, o);
    if (lane == 0) sred[warp] = ws;
    __syncthreads();
    tot = 0.f;
#pragma unroll
    for (int i = 0; i < 8; i++) tot += sred[i];
    float var = tot * (1.0f / D_MODEL);

    float y = df * rsqrtf(var + LN_EPS) * gs[d] + gb[d];
    g_u[idx] = y;
    __nv_bfloat16 h = __float2bfloat16(y);
    g_u_hi[idx] = h;
    g_u_lo[idx] = __float2bfloat16(y - __bfloat162float(h));
}

// ---------------------------------------------------------------------------
__global__ __launch_bounds__(96) void head_partial_kernel(const float* __restrict__ Wh)
{
    int d = blockIdx.x;
    int t = threadIdx.x;
    __shared__ float usm[BROWS][TOTAL_S];
    for (int i = t; i < BROWS * TOTAL_S; i += 96) {
        int bcc = i / TOTAL_S, s = i % TOTAL_S;
        usm[bcc][s] = g_u[(size_t)(bcc * TOTAL_S + s) * D_MODEL + d];
    }
    __syncthreads();
    float acc[BROWS];
#pragma unroll
    for (int b = 0; b < BROWS; b++) acc[b] = 0.f;
    for (int s = 0; s < TOTAL_S; s++) {
        float w = Wh[((size_t)d * TOTAL_S + s) * TGT + t];
#pragma unroll
        for (int b = 0; b < BROWS; b++) acc[b] += usm[b][s] * w;
    }
#pragma unroll
    for (int b = 0; b < BROWS; b++)
        g_part[((size_t)d * BROWS + b) * TGT + t] = acc[b];
}

__global__ __launch_bounds__(256) void head_reduce_kernel(
    const float* __restrict__ bh,
    const float* __restrict__ revin_w, const float* __restrict__ revin_b,
    float* __restrict__ out)
{
    int idx = blockIdx.x * blockDim.x + threadIdx.x;
    if (idx >= BROWS * TGT) return;
    int bcc = idx / TGT, t = idx % TGT;
    float acc = 0.f;
    for (int d = 0; d < D_MODEL; d++)
        acc += g_part[((size_t)d * BROWS + bcc) * TGT + t];
    acc += bh[t];
    int c = bcc & 7;
    out[idx] = (acc - revin_b[c]) / (revin_w[c] + 1e-10f) * g_std[bcc] + g_mean[bcc];
}

// ---------------------------------------------------------------------------
extern "C" void kernel_launch(void* const* d_in, const int* in_sizes, int n_in,
                              void* d_out, int out_size)
{
    const float* z       = (const float*)d_in[0];
    const float* revin_w = (const float*)d_in[1];
    const float* revin_b = (const float*)d_in[2];
    const float* Wf      = (const float*)d_in[3];
    const float* bf      = (const float*)d_in[4];
    const float* Wc      = (const float*)d_in[5];
    const float* bcoarse = (const float*)d_in[6];
    const float* Wpos    = (const float*)d_in[7];
    const float* WQ      = (const float*)d_in[8];
    const float* bQ      = (const float*)d_in[9];
    const float* WK      = (const float*)d_in[10];
    const float* bK      = (const float*)d_in[11];
    const float* WV      = (const float*)d_in[12];
    const float* bV      = (const float*)d_in[13];
    const float* WO      = (const float*)d_in[14];
    const float* bO      = (const float*)d_in[15];
    const float* ln1_s   = (const float*)d_in[16];
    const float* ln1_b   = (const float*)d_in[17];
    const float* ln2_s   = (const float*)d_in[18];
    const float* ln2_b   = (const float*)d_in[19];
    const float* F1      = (const float*)d_in[20];
    const float* c1      = (const float*)d_in[21];
    const float* F2      = (const float*)d_in[22];
    const float* c2      = (const float*)d_in[23];
    const float* Wh      = (const float*)d_in[24];
    const float* bh      = (const float*)d_in[25];
    float* out = (float*)d_out;

    float *u, *qkv, *tmp, *bqkv;
    __nv_bfloat16 *uh, *ul, *oh, *ol, *h1h, *h1l, *wth, *wtl;
    cudaGetSymbolAddress((void**)&u,    g_u);
    cudaGetSymbolAddress((void**)&qkv,  g_qkv);
    cudaGetSymbolAddress((void**)&tmp,  g_tmp);
    cudaGetSymbolAddress((void**)&bqkv, g_bqkv);
    cudaGetSymbolAddress((void**)&uh,   g_u_hi);
    cudaGetSymbolAddress((void**)&ul,   g_u_lo);
    cudaGetSymbolAddress((void**)&oh,   g_o_hi);
    cudaGetSymbolAddress((void**)&ol,   g_o_lo);
    cudaGetSymbolAddress((void**)&h1h,  g_h1_hi);
    cudaGetSymbolAddress((void**)&h1l,  g_h1_lo);
    cudaGetSymbolAddress((void**)&wth,  g_wt_hi);
    cudaGetSymbolAddress((void**)&wtl,  g_wt_lo);

    const int SMEM64 = 2 * (2 * 64 * ASTRIDE * 2 + 2 * 128 * ASTRIDE * 2);  // 110592
    cudaFuncSetAttribute(gemm_tc<0,64>, cudaFuncAttributeMaxDynamicSharedMemorySize, SMEM64);
    cudaFuncSetAttribute(gemm_tc<1,64>, cudaFuncAttributeMaxDynamicSharedMemorySize, SMEM64);
    cudaFuncSetAttribute(attn_kernel,   cudaFuncAttributeMaxDynamicSharedMemorySize, ATTN_SMEM);

    // launch order: 0 wsplit(+bias+stats), 1 embed, 2 QKV gemm, 3 attn
    wsplit_all_kernel<<<dim3(256, 8, NLAYERS), 256>>>(WQ, WK, WV, WO, F1, F2,
                                                      bQ, bK, bV, z);
    embed_kernel<<<dim3(TOTAL_S, BROWS), 256>>>(z, revin_w, revin_b,
                                                Wf, bf, Wc, bcoarse, Wpos);

    for (int l = 0; l < NLAYERS; l++) {
        const size_t L = (size_t)l * WSTRIDE;
        gemm_tc<0,64><<<dim3(6, 80), 256, SMEM64>>>(
            uh, ul, wth + L + WOFF_Q, wtl + L + WOFF_Q,
            bqkv + l * 768, qkv, nullptr, nullptr, 768, D_MODEL);
        attn_kernel<<<BROWS * NHEADS, 320, ATTN_SMEM>>>(
            l > 0 ? 1 : 0, l < NLAYERS - 1 ? 1 : 0);
        gemm_tc<0,64><<<dim3(2, 80), 256, SMEM64>>>(
            oh, ol, wth + L + WOFF_O, wtl + L + WOFF_O,
            bO + l * D_MODEL, tmp, nullptr, nullptr, D_MODEL, D_MODEL);
        resid_ln_kernel<<<SEQ, 256>>>(tmp, ln1_s + l * D_MODEL, ln1_b + l * D_MODEL);
        gemm_tc<1,64><<<dim3(8, 80), 256, SMEM64>>>(
            uh, ul, wth + L + WOFF_F1, wtl + L + WOFF_F1,
            c1 + l * DFF, nullptr, h1h, h1l, DFF, D_MODEL);
        gemm_tc<0,64><<<dim3(2, 80), 256, SMEM64>>>(
            h1h, h1l, wth + L + WOFF_F2, wtl + L + WOFF_F2,
            c2 + l * D_MODEL, tmp, nullptr, nullptr, D_MODEL, DFF);
        resid_ln_kernel<<<SEQ, 256>>>(tmp, ln2_s + l * D_MODEL, ln2_b + l * D_MODEL);
    }

    head_partial_kernel<<<D_MODEL, 96>>>(Wh);
    head_reduce_kernel<<<6, 256>>>(bh, revin_w, revin_b, out);
}

// round 14
// speedup vs baseline: 1.3149x; 1.0708x over previous
#include <cuda_runtime.h>
#include <cuda_bf16.h>
#include <math.h>
#include <stdint.h>

#define CTX      1024
#define BROWS    16
#define TOTAL_S  320
#define NF       256
#define D_MODEL  256
#define NHEADS   16
#define DK       16
#define DFF      1024
#define NLAYERS  4
#define TGT      96
#define SEQ      (BROWS * TOTAL_S)   // 5120
#define ATTN_SCALE 0.25f
#define LN_EPS   1e-5f

// ---------------------------------------------------------------------------
// warp MMA + cp.async + f32x2 helpers
// ---------------------------------------------------------------------------
__device__ __forceinline__ uint32_t smem_u32(const void* p) {
    uint32_t a;
    asm("{ .reg .u64 t; cvta.to.shared.u64 t, %1; cvt.u32.u64 %0, t; }"
        : "=r"(a) : "l"(p));
    return a;
}
__device__ __forceinline__ void ldsm_x4(uint32_t& r0, uint32_t& r1,
                                        uint32_t& r2, uint32_t& r3, uint32_t addr) {
    asm volatile("ldmatrix.sync.aligned.m8n8.x4.shared.b16 {%0,%1,%2,%3}, [%4];"
                 : "=r"(r0), "=r"(r1), "=r"(r2), "=r"(r3) : "r"(addr));
}
__device__ __forceinline__ void mma_bf16(float* c, const uint32_t* a, const uint32_t* b) {
    asm volatile(
        "mma.sync.aligned.m16n8k16.row.col.f32.bf16.bf16.f32 "
        "{%0,%1,%2,%3}, {%4,%5,%6,%7}, {%8,%9}, {%0,%1,%2,%3};"
        : "+f"(c[0]), "+f"(c[1]), "+f"(c[2]), "+f"(c[3])
        : "r"(a[0]), "r"(a[1]), "r"(a[2]), "r"(a[3]), "r"(b[0]), "r"(b[1]));
}
#define CP_ASYNC16(dst, src) \
    asm volatile("cp.async.cg.shared.global [%0], [%1], 16;" :: "r"(dst), "l"(src))
#define CP_COMMIT() asm volatile("cp.async.commit_group;" ::: "memory")
#define CP_WAIT0()  asm volatile("cp.async.wait_group 0;" ::: "memory")

// packed f32x2 (Blackwell): 2 fp32 FMA per instruction
#define FFMA2(acc, a, b) \
    asm("fma.rn.f32x2 %0, %1, %2, %0;" : "+l"(acc) : "l"(a), "l"(b))
#define MUL2(out, a, b) \
    asm("mul.rn.f32x2 %0, %1, %2;" : "=l"(out) : "l"(a), "l"(b))
__device__ __forceinline__ unsigned long long pack2(float lo, float hi) {
    unsigned long long r;
    asm("mov.b64 %0, {%1, %2};" : "=l"(r) : "f"(lo), "f"(hi));
    return r;
}
__device__ __forceinline__ void unpack2(unsigned long long v, float& lo, float& hi) {
    asm("mov.b64 {%0, %1}, %2;" : "=f"(lo), "=f"(hi) : "l"(v));
}

// ---------------------------------------------------------------------------
// scratch
// ---------------------------------------------------------------------------
__device__ __align__(256) float g_u[SEQ * D_MODEL];
__device__ __align__(256) float g_qkv[SEQ * 768];
__device__ __align__(256) float g_tmp[SEQ * D_MODEL];
__device__ __align__(256) float g_scores[BROWS * NHEADS * TOTAL_S * TOTAL_S]; // [bh][kk][q]
__device__ float g_mean[BROWS];
__device__ float g_std[BROWS];
__device__ __align__(256) float g_part[D_MODEL * BROWS * TGT];
__device__ __align__(256) float g_bqkv[NLAYERS * 768];

__device__ __align__(256) __nv_bfloat16 g_u_hi[SEQ * D_MODEL];
__device__ __align__(256) __nv_bfloat16 g_u_lo[SEQ * D_MODEL];
__device__ __align__(256) __nv_bfloat16 g_o_hi[SEQ * D_MODEL];
__device__ __align__(256) __nv_bfloat16 g_o_lo[SEQ * D_MODEL];
__device__ __align__(256) __nv_bfloat16 g_h1_hi[SEQ * DFF];
__device__ __align__(256) __nv_bfloat16 g_h1_lo[SEQ * DFF];
#define WOFF_Q   0
#define WOFF_K   65536
#define WOFF_V   131072
#define WOFF_O   196608
#define WOFF_F1  262144
#define WOFF_F2  524288
#define WSTRIDE  786432
__device__ __align__(256) __nv_bfloat16 g_wt_hi[NLAYERS * WSTRIDE];
__device__ __align__(256) __nv_bfloat16 g_wt_lo[NLAYERS * WSTRIDE];

// ---------------------------------------------------------------------------
// merged preprocessing: weight transpose/split, bias pack, RevIN stats
// ---------------------------------------------------------------------------
__global__ __launch_bounds__(256) void wsplit_all_kernel(
    const float* __restrict__ WQ, const float* __restrict__ WK,
    const float* __restrict__ WV, const float* __restrict__ WO,
    const float* __restrict__ F1, const float* __restrict__ F2,
    const float* __restrict__ bQ, const float* __restrict__ bK,
    const float* __restrict__ bV, const float* __restrict__ z)
{
    int kind = blockIdx.y, l = blockIdx.z, tile = blockIdx.x;
    __shared__ float t[32][33];

    if (kind == 6) {
        if (tile >= 3) return;
        int i = tile * 256 + threadIdx.x;
        if (i >= 768) return;
        float v = (i < 256) ? bQ[l * 256 + i]
                : (i < 512) ? bK[l * 256 + i - 256]
                            : bV[l * 256 + i - 512];
        g_bqkv[l * 768 + i] = v;
        return;
    }
    if (kind == 7) {
        if (l != 0 || tile >= BROWS) return;
        int r = tile, tid = threadIdx.x;
        float s = 0.f, s2 = 0.f;
        for (int i = tid; i < CTX; i += 256) {
            float v = z[r * CTX + i];
            s += v; s2 += v * v;
        }
        float* rs = &t[0][0];
        float* rq = rs + 256;
        rs[tid] = s; rq[tid] = s2;
        __syncthreads();
        for (int o = 128; o; o >>= 1) {
            if (tid < o) { rs[tid] += rs[tid + o]; rq[tid] += rq[tid + o]; }
            __syncthreads();
        }
        if (tid == 0) {
            float m = rs[0] / CTX;
            float var = rq[0] / CTX - m * m;
            g_mean[r] = m;
            g_std[r]  = sqrtf(var + LN_EPS);
        }
        return;
    }

    const float* W; int R, C; size_t inl, ooff;
    switch (kind) {
        case 0: W = WQ; R = 256;  C = 256;  inl = 65536;  ooff = WOFF_Q;  break;
        case 1: W = WK; R = 256;  C = 256;  inl = 65536;  ooff = WOFF_K;  break;
        case 2: W = WV; R = 256;  C = 256;  inl = 65536;  ooff = WOFF_V;  break;
        case 3: W = WO; R = 256;  C = 256;  inl = 65536;  ooff = WOFF_O;  break;
        case 4: W = F1; R = 256;  C = 1024; inl = 262144; ooff = WOFF_F1; break;
        default: W = F2; R = 1024; C = 256; inl = 262144; ooff = WOFF_F2; break;
    }
    int ct = C >> 5, rt = R >> 5;
    if (tile >= ct * rt) return;
    int c0 = (tile % ct) << 5, r0 = (tile / ct) << 5;
    const float* Wl = W + (size_t)l * inl;

    int tx = threadIdx.x & 31, ty = threadIdx.x >> 5;
#pragma unroll
    for (int i = 0; i < 32; i += 8)
        t[ty + i][tx] = Wl[(size_t)(r0 + ty + i) * C + c0 + tx];
    __syncthreads();
#pragma unroll
    for (int i = 0; i < 32; i += 8) {
        float x = t[tx][ty + i];
        size_t oi = (size_t)l * WSTRIDE + ooff + (size_t)(c0 + ty + i) * R + (r0 + tx);
        __nv_bfloat16 h = __float2bfloat16(x);
        g_wt_hi[oi] = h;
        g_wt_lo[oi] = __float2bfloat16(x - __bfloat162float(h));
    }
}

// ---------------------------------------------------------------------------
__global__ __launch_bounds__(256) void embed_kernel(
    const float* __restrict__ z,
    const float* __restrict__ revin_w, const float* __restrict__ revin_b,
    const float* __restrict__ Wf, const float* __restrict__ bf,
    const float* __restrict__ Wc, const float* __restrict__ bcoarse,
    const float* __restrict__ Wpos)
{
    int bch = blockIdx.y;
    int s   = blockIdx.x;
    int d   = threadIdx.x;
    int c   = bch & 7;

    __shared__ float patch[32];
    int plen, stride, p;
    const float* W; const float* bias;
    if (s < NF) { plen = 8;  stride = 4;  p = s;      W = Wf; bias = bf; }
    else        { plen = 32; stride = 16; p = s - NF; W = Wc; bias = bcoarse; }

    if (d < plen) {
        int t = p * stride + d;
        if (t > CTX - 1) t = CTX - 1;
        float zv = z[bch * CTX + t];
        patch[d] = (zv - g_mean[bch]) / g_std[bch] * revin_w[c] + revin_b[c];
    }
    __syncthreads();

    float acc = bias[d] + Wpos[s * D_MODEL + d];
    for (int i = 0; i < plen; i++) acc += patch[i] * W[i * D_MODEL + d];
    size_t idx = (size_t)(bch * TOTAL_S + s) * D_MODEL + d;
    g_u[idx] = acc;
    __nv_bfloat16 h = __float2bfloat16(acc);
    g_u_hi[idx] = h;
    g_u_lo[idx] = __float2bfloat16(acc - __bfloat162float(h));
}

// ---------------------------------------------------------------------------
// HMMA bf16x3 GEMM, cp.async 2-stage pipeline, K-chunk 64, MT=64.
// ---------------------------------------------------------------------------
#define ASTRIDE 72

template<int EPI, int MT>
__global__ __launch_bounds__(256) void gemm_tc(
    const __nv_bfloat16* __restrict__ Ah, const __nv_bfloat16* __restrict__ Al,
    const __nv_bfloat16* __restrict__ Bh, const __nv_bfloat16* __restrict__ Bl,
    const float* __restrict__ bias,
    float* __restrict__ Cf,
    __nv_bfloat16* __restrict__ Chi, __nv_bfloat16* __restrict__ Clo,
    int N, int K)
{
    constexpr int WNs = (MT == 128) ? 2 : 4;
    constexpr int NT  = 16 / WNs;
    constexpr int BUF_A = MT * ASTRIDE * 2;
    constexpr int BUF_B = 128 * ASTRIDE * 2;
    constexpr int STAGE = 2 * BUF_A + 2 * BUF_B;

    extern __shared__ char smem[];
    const uint32_t sbase = smem_u32(smem);

    const int tid = threadIdx.x;
    const int bm = blockIdx.y * MT, bn = blockIdx.x * 128;
    const int warp = tid >> 5, lane = tid & 31;
    const int wm = warp / WNs, wn = warp % WNs;

    const int sr = tid >> 3, sc = (tid & 7) * 8;

    float acc[2][NT][4];
#pragma unroll
    for (int mt = 0; mt < 2; mt++)
#pragma unroll
        for (int nt = 0; nt < NT; nt++)
#pragma unroll
            for (int i = 0; i < 4; i++) acc[mt][nt][i] = 0.f;

    const int gg = lane >> 3, l7 = lane & 7;
    const int a_row = (gg & 1) * 8 + l7;
    const int a_kb  = (gg >> 1) * 16;
    const int b_row = (gg >> 1) * 8 + l7;
    const int b_kb  = (gg & 1) * 16;

    const int nchunk = K >> 6;

#define STAGE_LOAD(kc, s) do { \
        const int _k0 = (kc) << 6; \
        uint32_t _base = sbase + (s) * STAGE; \
        _Pragma("unroll") \
        for (int i = 0; i < MT / 32; i++) { \
            int r = sr + i * 32; \
            uint32_t so = _base + r * 144 + sc * 2; \
            CP_ASYNC16(so, Ah + (size_t)(bm + r) * K + _k0 + sc); \
            CP_ASYNC16(so + BUF_A, Al + (size_t)(bm + r) * K + _k0 + sc); \
        } \
        _Pragma("unroll") \
        for (int i = 0; i < 4; i++) { \
            int r = sr + i * 32; \
            uint32_t so = _base + 2 * BUF_A + r * 144 + sc * 2; \
            CP_ASYNC16(so, Bh + (size_t)(bn + r) * K + _k0 + sc); \
            CP_ASYNC16(so + BUF_B, Bl + (size_t)(bn + r) * K + _k0 + sc); \
        } \
        CP_COMMIT(); \
    } while (0)

    STAGE_LOAD(0, 0);

    for (int kc = 0; kc < nchunk; kc++) {
        CP_WAIT0();
        __syncthreads();
        if (kc + 1 < nchunk) STAGE_LOAD(kc + 1, (kc + 1) & 1);

        const uint32_t base = sbase + (kc & 1) * STAGE;
        const uint32_t uAh = base, uAl = base + BUF_A;
        const uint32_t uBh = base + 2 * BUF_A, uBl = uBh + BUF_B;

#pragma unroll
        for (int ks = 0; ks < 4; ks++) {
            uint32_t ah[2][4], al[2][4], bh[NT][2], bl[NT][2];
#pragma unroll
            for (int mt = 0; mt < 2; mt++) {
                int row = wm * 32 + mt * 16 + a_row;
                uint32_t off = (uint32_t)(row * 144 + ks * 32 + a_kb);
                ldsm_x4(ah[mt][0], ah[mt][1], ah[mt][2], ah[mt][3], uAh + off);
                ldsm_x4(al[mt][0], al[mt][1], al[mt][2], al[mt][3], uAl + off);
            }
#pragma unroll
            for (int j = 0; j < NT / 2; j++) {
                int row = wn * (128 / WNs) + j * 16 + b_row;
                uint32_t off = (uint32_t)(row * 144 + ks * 32 + b_kb);
                uint32_t r0, r1, r2, r3;
                ldsm_x4(r0, r1, r2, r3, uBh + off);
                bh[2 * j][0] = r0; bh[2 * j][1] = r1;
                bh[2 * j + 1][0] = r2; bh[2 * j + 1][1] = r3;
                ldsm_x4(r0, r1, r2, r3, uBl + off);
                bl[2 * j][0] = r0; bl[2 * j][1] = r1;
                bl[2 * j + 1][0] = r2; bl[2 * j + 1][1] = r3;
            }
#pragma unroll
            for (int mt = 0; mt < 2; mt++)
#pragma unroll
                for (int nt = 0; nt < NT; nt++) {
                    mma_bf16(acc[mt][nt], ah[mt], bh[nt]);
                    mma_bf16(acc[mt][nt], ah[mt], bl[nt]);
                    mma_bf16(acc[mt][nt], al[mt], bh[nt]);
                }
        }
        __syncthreads();
    }
#undef STAGE_LOAD

#pragma unroll
    for (int mt = 0; mt < 2; mt++) {
        int row0 = bm + wm * 32 + mt * 16 + (lane >> 2);
#pragma unroll
        for (int nt = 0; nt < NT; nt++) {
            int col = bn + wn * (128 / WNs) + nt * 8 + (lane & 3) * 2;
            float b0 = bias[col], b1 = bias[col + 1];
            float v0 = acc[mt][nt][0] + b0, v1 = acc[mt][nt][1] + b1;
            float v2 = acc[mt][nt][2] + b0, v3 = acc[mt][nt][3] + b1;
            if (EPI == 0) {
                float2 p0 = {v0, v1}, p1 = {v2, v3};
                *(float2*)&Cf[(size_t)row0 * N + col] = p0;
                *(float2*)&Cf[(size_t)(row0 + 8) * N + col] = p1;
            } else {
                v0 = 0.5f * v0 * (1.0f + erff(v0 * 0.7071067811865475f));
                v1 = 0.5f * v1 * (1.0f + erff(v1 * 0.7071067811865475f));
                v2 = 0.5f * v2 * (1.0f + erff(v2 * 0.7071067811865475f));
                v3 = 0.5f * v3 * (1.0f + erff(v3 * 0.7071067811865475f));
                __nv_bfloat162 hh, ll;
                hh.x = __float2bfloat16(v0); hh.y = __float2bfloat16(v1);
                ll.x = __float2bfloat16(v0 - __bfloat162float(hh.x));
                ll.y = __float2bfloat16(v1 - __bfloat162float(hh.y));
                *(__nv_bfloat162*)&Chi[(size_t)row0 * N + col] = hh;
                *(__nv_bfloat162*)&Clo[(size_t)row0 * N + col] = ll;
                hh.x = __float2bfloat16(v2); hh.y = __float2bfloat16(v3);
                ll.x = __float2bfloat16(v2 - __bfloat162float(hh.x));
                ll.y = __float2bfloat16(v3 - __bfloat162float(hh.y));
                *(__nv_bfloat162*)&Chi[(size_t)(row0 + 8) * N + col] = hh;
                *(__nv_bfloat162*)&Clo[(size_t)(row0 + 8) * N + col] = ll;
            }
        }
    }
}

// ---------------------------------------------------------------------------
// fused attention v4: 2 q-rows per thread (rows tid and tid+160), 160
// threads/CTA — each broadcast K/V LDS serves both rows (LDS halved).
// Online softmax; f32x2 FMA; scores transposed [bh][kk][q].
// ---------------------------------------------------------------------------
#define ATTN_SMEM (3 * TOTAL_S * DK * 4)   // 61440 B

__global__ __launch_bounds__(160) void attn_kernel(int use_prev, int wr)
{
    extern __shared__ float asm_f[];
    float* Ks = asm_f;
    float* Vs = Ks + TOTAL_S * DK;
    float* Qs = Vs + TOTAL_S * DK;

    int bh = blockIdx.x;
    int bc = bh >> 4, h = bh & 15;
    int tid = threadIdx.x;             // q-rows tid and tid+160

    for (int i = tid; i < TOTAL_S * 4; i += 160) {
        int s = i >> 2, c = i & 3;
        const float4* src = (const float4*)&g_qkv[(size_t)(bc * TOTAL_S + s) * 768 + (h << 4)];
        *(float4*)&Qs[s * DK + c * 4] = src[c];
        *(float4*)&Ks[s * DK + c * 4] = src[64 + c];
        *(float4*)&Vs[s * DK + c * 4] = src[128 + c];
    }
    __syncthreads();

    const int ra = tid, rb = tid + 160;
    unsigned long long qa2[8], qb2[8];
    {
        const ulonglong2* qpa = (const ulonglong2*)&Qs[ra * DK];
        const ulonglong2* qpb = (const ulonglong2*)&Qs[rb * DK];
#pragma unroll
        for (int c = 0; c < 4; c++) {
            ulonglong2 va = qpa[c], vb = qpb[c];
            qa2[2 * c] = va.x; qa2[2 * c + 1] = va.y;
            qb2[2 * c] = vb.x; qb2[2 * c + 1] = vb.y;
        }
    }

    float ma = -1e30f, mb = -1e30f, da = 0.f, db = 0.f;
    unsigned long long oa2[8], ob2[8];
#pragma unroll
    for (int c = 0; c < 8; c++) { oa2[c] = 0ULL; ob2[c] = 0ULL; }

    float* srow = &g_scores[(size_t)bh * TOTAL_S * TOTAL_S];  // [kk][q]

#pragma unroll 1
    for (int blk = 0; blk < 40; blk++) {
        float sa[8], sb[8];
#pragma unroll
        for (int t = 0; t < 8; t++) {
            int kk = blk * 8 + t;
            const ulonglong2* kp = (const ulonglong2*)&Ks[kk * DK];
            unsigned long long aa2 = 0ULL, ab2 = 0ULL;
#pragma unroll
            for (int c = 0; c < 4; c++) {
                ulonglong2 kv = kp[c];                  // broadcast LDS.128
                FFMA2(aa2, qa2[2 * c], kv.x);
                FFMA2(aa2, qa2[2 * c + 1], kv.y);
                FFMA2(ab2, qb2[2 * c], kv.x);
                FFMA2(ab2, qb2[2 * c + 1], kv.y);
            }
            float lo, hi;
            unpack2(aa2, lo, hi);
            float s_a = (lo + hi) * ATTN_SCALE;
            unpack2(ab2, lo, hi);
            float s_b = (lo + hi) * ATTN_SCALE;
            if (use_prev) {
                s_a += srow[(size_t)kk * TOTAL_S + ra];
                s_b += srow[(size_t)kk * TOTAL_S + rb];
            }
            sa[t] = s_a; sb[t] = s_b;
            if (wr) {
                srow[(size_t)kk * TOTAL_S + ra] = s_a;
                srow[(size_t)kk * TOTAL_S + rb] = s_b;
            }
        }
        float bma = sa[0], bmb = sb[0];
#pragma unroll
        for (int t = 1; t < 8; t++) { bma = fmaxf(bma, sa[t]); bmb = fmaxf(bmb, sb[t]); }
        float mna = fmaxf(ma, bma), mnb = fmaxf(mb, bmb);
        float ca = __expf(ma - mna), cb = __expf(mb - mnb);
        da *= ca; db *= cb;
        unsigned long long ca2 = pack2(ca, ca), cb2 = pack2(cb, cb);
#pragma unroll
        for (int c = 0; c < 8; c++) { MUL2(oa2[c], oa2[c], ca2); MUL2(ob2[c], ob2[c], cb2); }
#pragma unroll
        for (int t = 0; t < 8; t++) {
            int kk = blk * 8 + t;
            float pa = __expf(sa[t] - mna), pb = __expf(sb[t] - mnb);
            da += pa; db += pb;
            unsigned long long pa2 = pack2(pa, pa), pb2 = pack2(pb, pb);
            const ulonglong2* vp = (const ulonglong2*)&Vs[kk * DK];
#pragma unroll
            for (int c = 0; c < 4; c++) {
                ulonglong2 vv = vp[c];                  // broadcast LDS.128
                FFMA2(oa2[2 * c], pa2, vv.x);
                FFMA2(oa2[2 * c + 1], pa2, vv.y);
                FFMA2(ob2[2 * c], pb2, vv.x);
                FFMA2(ob2[2 * c + 1], pb2, vv.y);
            }
        }
        ma = mna; mb = mnb;
    }

    float inva = 1.f / da, invb = 1.f / db;
    size_t oba = (size_t)(bc * TOTAL_S + ra) * D_MODEL + (h << 4);
    size_t obb = (size_t)(bc * TOTAL_S + rb) * D_MODEL + (h << 4);
#pragma unroll
    for (int c = 0; c < 8; c++) {
        float v0, v1;
        unpack2(oa2[c], v0, v1);
        v0 *= inva; v1 *= inva;
        __nv_bfloat162 hh, ll;
        hh.x = __float2bfloat16(v0); hh.y = __float2bfloat16(v1);
        ll.x = __float2bfloat16(v0 - __bfloat162float(hh.x));
        ll.y = __float2bfloat16(v1 - __bfloat162float(hh.y));
        *(__nv_bfloat162*)&g_o_hi[oba + c * 2] = hh;
        *(__nv_bfloat162*)&g_o_lo[oba + c * 2] = ll;
        unpack2(ob2[c], v0, v1);
        v0 *= invb; v1 *= invb;
        hh.x = __float2bfloat16(v0); hh.y = __float2bfloat16(v1);
        ll.x = __float2bfloat16(v0 - __bfloat162float(hh.x));
        ll.y = __float2bfloat16(v1 - __bfloat162float(hh.y));
        *(__nv_bfloat162*)&g_o_hi[obb + c * 2] = hh;
        *(__nv_bfloat162*)&g_o_lo[obb + c * 2] = ll;
    }
}

// ---------------------------------------------------------------------------
__global__ __launch_bounds__(256) void resid_ln_kernel(
    const float* __restrict__ delta,
    const float* __restrict__ gs, const float* __restrict__ gb)
{
    int row = blockIdx.x;
    int d = threadIdx.x;
    int warp = d >> 5, lane = d & 31;
    size_t idx = (size_t)row * D_MODEL + d;
    float t = g_u[idx] + delta[idx];

    __shared__ float sred[8];
    float ws = t;
#pragma unroll
    for (int o = 16; o; o >>= 1) ws += __shfl_xor_sync(0xffffffffu, ws, o);
    if (lane == 0) sred[warp] = ws;
    __syncthreads();
    float tot = 0.f;
#pragma unroll
    for (int i = 0; i < 8; i++) tot += sred[i];
    float mean = tot * (1.0f / D_MODEL);
    __syncthreads();

    float df = t - mean;
    ws = df * df;
#pragma unroll
    for (int o = 16; o; o >>= 1) ws += __shfl_xor_sync(0xffffffffu, ws, o);
    if (lane == 0) sred[warp] = ws;
    __syncthreads();
    tot = 0.f;
#pragma unroll
    for (int i = 0; i < 8; i++) tot += sred[i];
    float var = tot * (1.0f / D_MODEL);

    float y = df * rsqrtf(var + LN_EPS) * gs[d] + gb[d];
    g_u[idx] = y;
    __nv_bfloat16 h = __float2bfloat16(y);
    g_u_hi[idx] = h;
    g_u_lo[idx] = __float2bfloat16(y - __bfloat162float(h));
}

// ---------------------------------------------------------------------------
__global__ __launch_bounds__(96) void head_partial_kernel(const float* __restrict__ Wh)
{
    int d = blockIdx.x;
    int t = threadIdx.x;
    __shared__ float usm[BROWS][TOTAL_S];
    for (int i = t; i < BROWS * TOTAL_S; i += 96) {
        int bcc = i / TOTAL_S, s = i % TOTAL_S;
        usm[bcc][s] = g_u[(size_t)(bcc * TOTAL_S + s) * D_MODEL + d];
    }
    __syncthreads();
    float acc[BROWS];
#pragma unroll
    for (int b = 0; b < BROWS; b++) acc[b] = 0.f;
    for (int s = 0; s < TOTAL_S; s++) {
        float w = Wh[((size_t)d * TOTAL_S + s) * TGT + t];
#pragma unroll
        for (int b = 0; b < BROWS; b++) acc[b] += usm[b][s] * w;
    }
#pragma unroll
    for (int b = 0; b < BROWS; b++)
        g_part[((size_t)d * BROWS + b) * TGT + t] = acc[b];
}

__global__ __launch_bounds__(256) void head_reduce_kernel(
    const float* __restrict__ bh,
    const float* __restrict__ revin_w, const float* __restrict__ revin_b,
    float* __restrict__ out)
{
    int idx = blockIdx.x * blockDim.x + threadIdx.x;
    if (idx >= BROWS * TGT) return;
    int bcc = idx / TGT, t = idx % TGT;
    float acc = 0.f;
    for (int d = 0; d < D_MODEL; d++)
        acc += g_part[((size_t)d * BROWS + bcc) * TGT + t];
    acc += bh[t];
    int c = bcc & 7;
    out[idx] = (acc - revin_b[c]) / (revin_w[c] + 1e-10f) * g_std[bcc] + g_mean[bcc];
}

// ---------------------------------------------------------------------------
extern "C" void kernel_launch(void* const* d_in, const int* in_sizes, int n_in,
                              void* d_out, int out_size)
{
    const float* z       = (const float*)d_in[0];
    const float* revin_w = (const float*)d_in[1];
    const float* revin_b = (const float*)d_in[2];
    const float* Wf      = (const float*)d_in[3];
    const float* bf      = (const float*)d_in[4];
    const float* Wc      = (const float*)d_in[5];
    const float* bcoarse = (const float*)d_in[6];
    const float* Wpos    = (const float*)d_in[7];
    const float* WQ      = (const float*)d_in[8];
    const float* bQ      = (const float*)d_in[9];
    const float* WK      = (const float*)d_in[10];
    const float* bK      = (const float*)d_in[11];
    const float* WV      = (const float*)d_in[12];
    const float* bV      = (const float*)d_in[13];
    const float* WO      = (const float*)d_in[14];
    const float* bO      = (const float*)d_in[15];
    const float* ln1_s   = (const float*)d_in[16];
    const float* ln1_b   = (const float*)d_in[17];
    const float* ln2_s   = (const float*)d_in[18];
    const float* ln2_b   = (const float*)d_in[19];
    const float* F1      = (const float*)d_in[20];
    const float* c1      = (const float*)d_in[21];
    const float* F2      = (const float*)d_in[22];
    const float* c2      = (const float*)d_in[23];
    const float* Wh      = (const float*)d_in[24];
    const float* bh      = (const float*)d_in[25];
    float* out = (float*)d_out;

    float *u, *qkv, *tmp, *bqkv;
    __nv_bfloat16 *uh, *ul, *oh, *ol, *h1h, *h1l, *wth, *wtl;
    cudaGetSymbolAddress((void**)&u,    g_u);
    cudaGetSymbolAddress((void**)&qkv,  g_qkv);
    cudaGetSymbolAddress((void**)&tmp,  g_tmp);
    cudaGetSymbolAddress((void**)&bqkv, g_bqkv);
    cudaGetSymbolAddress((void**)&uh,   g_u_hi);
    cudaGetSymbolAddress((void**)&ul,   g_u_lo);
    cudaGetSymbolAddress((void**)&oh,   g_o_hi);
    cudaGetSymbolAddress((void**)&ol,   g_o_lo);
    cudaGetSymbolAddress((void**)&h1h,  g_h1_hi);
    cudaGetSymbolAddress((void**)&h1l,  g_h1_lo);
    cudaGetSymbolAddress((void**)&wth,  g_wt_hi);
    cudaGetSymbolAddress((void**)&wtl,  g_wt_lo);

    const int SMEM64 = 2 * (2 * 64 * ASTRIDE * 2 + 2 * 128 * ASTRIDE * 2);  // 110592
    cudaFuncSetAttribute(gemm_tc<0,64>, cudaFuncAttributeMaxDynamicSharedMemorySize, SMEM64);
    cudaFuncSetAttribute(gemm_tc<1,64>, cudaFuncAttributeMaxDynamicSharedMemorySize, SMEM64);
    cudaFuncSetAttribute(attn_kernel,   cudaFuncAttributeMaxDynamicSharedMemorySize, ATTN_SMEM);

    // launch order: 0 wsplit(+bias+stats), 1 embed, 2 QKV gemm, 3 attn
    wsplit_all_kernel<<<dim3(256, 8, NLAYERS), 256>>>(WQ, WK, WV, WO, F1, F2,
                                                      bQ, bK, bV, z);
    embed_kernel<<<dim3(TOTAL_S, BROWS), 256>>>(z, revin_w, revin_b,
                                                Wf, bf, Wc, bcoarse, Wpos);

    for (int l = 0; l < NLAYERS; l++) {
        const size_t L = (size_t)l * WSTRIDE;
        gemm_tc<0,64><<<dim3(6, 80), 256, SMEM64>>>(
            uh, ul, wth + L + WOFF_Q, wtl + L + WOFF_Q,
            bqkv + l * 768, qkv, nullptr, nullptr, 768, D_MODEL);
        attn_kernel<<<BROWS * NHEADS, 160, ATTN_SMEM>>>(
            l > 0 ? 1 : 0, l < NLAYERS - 1 ? 1 : 0);
        gemm_tc<0,64><<<dim3(2, 80), 256, SMEM64>>>(
            oh, ol, wth + L + WOFF_O, wtl + L + WOFF_O,
            bO + l * D_MODEL, tmp, nullptr, nullptr, D_MODEL, D_MODEL);
        resid_ln_kernel<<<SEQ, 256>>>(tmp, ln1_s + l * D_MODEL, ln1_b + l * D_MODEL);
        gemm_tc<1,64><<<dim3(8, 80), 256, SMEM64>>>(
            uh, ul, wth + L + WOFF_F1, wtl + L + WOFF_F1,
            c1 + l * DFF, nullptr, h1h, h1l, DFF, D_MODEL);
        gemm_tc<0,64><<<dim3(2, 80), 256, SMEM64>>>(
            h1h, h1l, wth + L + WOFF_F2, wtl + L + WOFF_F2,
            c2 + l * D_MODEL, tmp, nullptr, nullptr, D_MODEL, DFF);
        resid_ln_kernel<<<SEQ, 256>>>(tmp, ln2_s + l * D_MODEL, ln2_b + l * D_MODEL);
    }

    head_partial_kernel<<<D_MODEL, 96>>>(Wh);
    head_reduce_kernel<<<6, 256>>>(bh, revin_w, revin_b, out);
}